// round 13
// baseline (speedup 1.0000x reference)
#include <cuda_runtime.h>
#include <cuda_fp16.h>
#include <cstdint>
#include <cstddef>

#define NROWS 8192
#define CROWS 4096
#define QDIM  512
#define INNER 512
#define KVDIM 1024
#define MCTX  2048

// ---------------- static scratch (fp16) --------------------------------------
__device__ __align__(256) __half g_xh [NROWS * QDIM];
__device__ __align__(256) __half g_ch [CROWS * QDIM];
__device__ __align__(256) __half g_wqh[INNER * QDIM];
__device__ __align__(256) __half g_wkh[KVDIM * QDIM];
__device__ __align__(256) __half g_woh[INNER * INNER];
__device__ __align__(256) __half g_qh [NROWS * INNER];
__device__ __align__(256) __half g_kvh[CROWS * KVDIM];
__device__ __align__(256) __half g_aoh[NROWS * INNER], g_aol[NROWS * INNER];

// ---------------- helpers ----------------------------------------------------
#define SWZ(off) ((off) ^ (((off) >> 3) & 0x70))

static __device__ __forceinline__ uint32_t smem_u32(const void* p) {
    uint32_t a;
    asm("{ .reg .u64 t; cvta.to.shared.u64 t, %1; cvt.u32.u64 %0, t; }"
        : "=r"(a) : "l"(p));
    return a;
}
static __device__ __forceinline__ void ldsm4(uint32_t& r0, uint32_t& r1,
                                             uint32_t& r2, uint32_t& r3, uint32_t a) {
    asm volatile("ldmatrix.sync.aligned.m8n8.x4.shared.b16 {%0,%1,%2,%3}, [%4];"
                 : "=r"(r0), "=r"(r1), "=r"(r2), "=r"(r3) : "r"(a));
}
static __device__ __forceinline__ void ldsm4t(uint32_t& r0, uint32_t& r1,
                                              uint32_t& r2, uint32_t& r3, uint32_t a) {
    asm volatile("ldmatrix.sync.aligned.m8n8.x4.trans.shared.b16 {%0,%1,%2,%3}, [%4];"
                 : "=r"(r0), "=r"(r1), "=r"(r2), "=r"(r3) : "r"(a));
}
static __device__ __forceinline__ void mma16816(float* c, const uint32_t* a,
                                                uint32_t b0, uint32_t b1) {
    asm volatile("mma.sync.aligned.m16n8k16.row.col.f32.f16.f16.f32 "
                 "{%0,%1,%2,%3}, {%4,%5,%6,%7}, {%8,%9}, {%0,%1,%2,%3};"
                 : "+f"(c[0]), "+f"(c[1]), "+f"(c[2]), "+f"(c[3])
                 : "r"(a[0]), "r"(a[1]), "r"(a[2]), "r"(a[3]), "r"(b0), "r"(b1));
}
static __device__ __forceinline__ uint32_t packh(float a, float b) {
    __half2 t = __floats2half2_rn(a, b);
    return *(uint32_t*)&t;
}
// fp16x2 exp2 on the packed pair (one MUFU op for two elements)
static __device__ __forceinline__ uint32_t ex2_h2(uint32_t h2) {
    asm("ex2.approx.f16x2 %0, %0;" : "+r"(h2));
    return h2;
}
#define CP_ASYNC(dst, src) \
    asm volatile("cp.async.cg.shared.global [%0], [%1], 16;" \
                 :: "r"(dst), "l"(src) : "memory")
#define CP_COMMIT() asm volatile("cp.async.commit_group;" ::: "memory")
#define CP_WAIT(n)  asm volatile("cp.async.wait_group %0;" :: "n"(n) : "memory")

// ---------------- conversion kernels ------------------------------------------
__global__ void split_inputs(const float4* __restrict__ x, const float4* __restrict__ c,
                             uint2* __restrict__ xh, uint2* __restrict__ ch,
                             int n1, int n2, float qscale) {
    int i = blockIdx.x * 256 + threadIdx.x;
    const float4* in;
    uint2* oh;
    float scale;
    if (i < n1) { in = x; oh = xh; scale = qscale; }
    else {
        i -= n1;
        if (i >= n2) return;
        in = c; oh = ch; scale = 1.0f;
    }
    float4 v = in[i];
    oh[i] = make_uint2(packh(v.x * scale, v.y * scale),
                       packh(v.z * scale, v.w * scale));
}

__global__ __launch_bounds__(256)
void split_transpose3(const float* __restrict__ w0, const float* __restrict__ w1,
                      const float* __restrict__ w2,
                      __half* __restrict__ oh0, __half* __restrict__ oh1,
                      __half* __restrict__ oh2) {
    const int z = blockIdx.z;
    const float* in = (z == 0) ? w0 : (z == 1) ? w1 : w2;
    __half* oh = (z == 0) ? oh0 : (z == 1) ? oh1 : oh2;
    const int N = (z == 1) ? KVDIM : INNER;
    const int K = QDIM;
    const int n0 = blockIdx.x * 32;
    if (n0 >= N) return;

    __shared__ float t[64][33];
    const int tid = threadIdx.x, tx = tid & 31, ty = tid >> 5;
    const int k0 = blockIdx.y * 64;
    #pragma unroll
    for (int r = ty; r < 64; r += 8)
        t[r][tx] = in[(size_t)(k0 + r) * N + n0 + tx];
    __syncthreads();
    #pragma unroll
    for (int r = ty; r < 32; r += 8) {
        int n = n0 + r;
        *(uint32_t*)(oh + (size_t)n * K + k0 + tx * 2) =
            packh(t[tx * 2][r], t[tx * 2 + 1][r]);
    }
}

// ---------------- HMMA GEMM core (device body) --------------------------------
#define GSTG(s) ((s) * 49152)
#define G_SM_TOTAL 98304

template <int MODE, int TERMS>   // MODE 1: fp32+bias; MODE 2: fp16 hi; MODE 0: hi/lo
static __device__ __forceinline__
void gemm_body(const __half* __restrict__ ah, const __half* __restrict__ al,
               const __half* __restrict__ bth,
               __half* __restrict__ coh, __half* __restrict__ col_,
               float* __restrict__ cf, const float* __restrict__ bias,
               int M, int N, int K, int bm, int bn, char* sm)
{
    const uint32_t sbase = smem_u32(sm);
    const int tid = threadIdx.x, warp = tid >> 5, lane = tid & 31;
    const int wm = warp >> 2, wn = warp & 3;

    float c[4][4][4] = {};

    const int a_row = (lane & 15), a_cb = (lane >> 4) * 16;
    const int b_row = (lane & 7) + (lane >> 4) * 8, b_cb = ((lane >> 3) & 1) * 16;

    const int NCH = K >> 6;

    #pragma unroll
    for (int p = 0; p < 2; p++) {
        const uint32_t st = sbase + GSTG(p);
        #pragma unroll
        for (int i = 0; i < 4; i++) {
            int idx = tid + i * 256;
            int r = idx >> 3, cc = idx & 7;
            uint32_t off = SWZ(r * 128 + cc * 16);
            size_t ga = (size_t)(bm + r) * K + p * 64 + cc * 8;
            size_t gb = (size_t)(bn + r) * K + p * 64 + cc * 8;
            CP_ASYNC(st + 0 + off, ah + ga);
            if (TERMS == 2) CP_ASYNC(st + 16384 + off, al + ga);
            CP_ASYNC(st + 32768 + off, bth + gb);
        }
        CP_COMMIT();
    }

    for (int it = 0; it < NCH; it++) {
        if (it + 1 < NCH) CP_WAIT(1); else CP_WAIT(0);
        __syncthreads();

        const uint32_t ah_s = sbase + GSTG(it & 1);
        const uint32_t al_s = ah_s + 16384;
        const uint32_t bh_s = ah_s + 32768;

        #pragma unroll
        for (int ks = 0; ks < 4; ks++) {
            uint32_t afh[4][4], afl[4][4], bfr[4][2];
            #pragma unroll
            for (int mt = 0; mt < 4; mt++) {
                int row = wm * 64 + mt * 16 + a_row;
                uint32_t so = SWZ(row * 128 + ks * 32 + a_cb);
                ldsm4(afh[mt][0], afh[mt][1], afh[mt][2], afh[mt][3], ah_s + so);
                if (TERMS == 2)
                    ldsm4(afl[mt][0], afl[mt][1], afl[mt][2], afl[mt][3], al_s + so);
            }
            #pragma unroll
            for (int np = 0; np < 2; np++) {
                int row = wn * 32 + np * 16 + b_row;
                uint32_t r0, r1, r2, r3;
                ldsm4(r0, r1, r2, r3, bh_s + SWZ(row * 128 + ks * 32 + b_cb));
                bfr[np*2][0] = r0; bfr[np*2][1] = r1;
                bfr[np*2+1][0] = r2; bfr[np*2+1][1] = r3;
            }
            #pragma unroll
            for (int mt = 0; mt < 4; mt++)
                #pragma unroll
                for (int nt = 0; nt < 4; nt++) {
                    mma16816(c[mt][nt], afh[mt], bfr[nt][0], bfr[nt][1]);
                    if (TERMS == 2)
                        mma16816(c[mt][nt], afl[mt], bfr[nt][0], bfr[nt][1]);
                }
        }
        __syncthreads();

        if (it + 2 < NCH) {
            const uint32_t st = sbase + GSTG(it & 1);
            const int k0 = (it + 2) << 6;
            #pragma unroll
            for (int i = 0; i < 4; i++) {
                int idx = tid + i * 256;
                int r = idx >> 3, cc = idx & 7;
                uint32_t off = SWZ(r * 128 + cc * 16);
                size_t ga = (size_t)(bm + r) * K + k0 + cc * 8;
                size_t gb = (size_t)(bn + r) * K + k0 + cc * 8;
                CP_ASYNC(st + 0 + off, ah + ga);
                if (TERMS == 2) CP_ASYNC(st + 16384 + off, al + ga);
                CP_ASYNC(st + 32768 + off, bth + gb);
            }
            CP_COMMIT();
        }
    }

    #pragma unroll
    for (int mt = 0; mt < 4; mt++) {
        int row0 = bm + wm * 64 + mt * 16 + (lane >> 2);
        #pragma unroll
        for (int nt = 0; nt < 4; nt++) {
            int col = bn + wn * 32 + nt * 8 + (lane & 3) * 2;
            float v0 = c[mt][nt][0], v1 = c[mt][nt][1];
            float v2 = c[mt][nt][2], v3 = c[mt][nt][3];
            if (MODE == 1) {
                float b0 = bias[col], b1 = bias[col + 1];
                *(float2*)(cf + (size_t)row0 * N + col)       = make_float2(v0 + b0, v1 + b1);
                *(float2*)(cf + (size_t)(row0 + 8) * N + col) = make_float2(v2 + b0, v3 + b1);
            } else {
                uint32_t h01 = packh(v0, v1), h23 = packh(v2, v3);
                *(uint32_t*)(coh  + (size_t)row0 * N + col)       = h01;
                *(uint32_t*)(coh  + (size_t)(row0 + 8) * N + col) = h23;
                if (MODE == 0) {
                    __half2 H01 = *(__half2*)&h01, H23 = *(__half2*)&h23;
                    uint32_t l01 = packh(v0 - __low2float(H01), v1 - __high2float(H01));
                    uint32_t l23 = packh(v2 - __low2float(H23), v3 - __high2float(H23));
                    *(uint32_t*)(col_ + (size_t)row0 * N + col)       = l01;
                    *(uint32_t*)(col_ + (size_t)(row0 + 8) * N + col) = l23;
                }
            }
        }
    }
}

// Fused Q-proj + KV-proj launch: 512 CTAs, 1-term, fp16-hi out.
__global__ __launch_bounds__(256, 2)
void mm_gemm_qkv(const __half* __restrict__ xh, const __half* __restrict__ wqh,
                 __half* __restrict__ qh,
                 const __half* __restrict__ ch, const __half* __restrict__ wkh,
                 __half* __restrict__ kvh)
{
    extern __shared__ __align__(128) char sm[];
    const int bid = blockIdx.x;
    if (bid < 256) {
        int bn = (bid & 3) * 128, bm = (bid >> 2) * 128;
        gemm_body<2, 1>(xh, nullptr, wqh, qh, nullptr, nullptr, nullptr,
                        NROWS, INNER, QDIM, bm, bn, sm);
    } else {
        int t = bid - 256;
        int bn = (t & 7) * 128, bm = (t >> 3) * 128;
        gemm_body<2, 1>(ch, nullptr, wkh, kvh, nullptr, nullptr, nullptr,
                        CROWS, KVDIM, QDIM, bm, bn, sm);
    }
}

// O projection: 2-term (attn-out hi/lo), fp32 + bias
__global__ __launch_bounds__(256, 2)
void mm_gemm_o(const __half* __restrict__ aoh, const __half* __restrict__ aol,
               const __half* __restrict__ woh, float* __restrict__ out,
               const float* __restrict__ bias)
{
    extern __shared__ __align__(128) char sm[];
    gemm_body<1, 2>(aoh, aol, woh, nullptr, nullptr, out, bias,
                    NROWS, INNER, INNER, blockIdx.y * 128, blockIdx.x * 128, sm);
}

// ---------------- HMMA flash attention ----------------------------------------
// exp via ex2.approx.f16x2 on packed score pairs (1 MUFU per 2 elements).
#define AQ_H 0
#define ASTG(s) (16384 + (s) * 32768)
#define ALBUF 81920
#define A_SM_TOTAL 82944

__global__ __launch_bounds__(256, 1)
void mm_attn(const __half* __restrict__ qh, const __half* __restrict__ kvh,
             __half* __restrict__ aoh, __half* __restrict__ aol)
{
    extern __shared__ __align__(128) char sm[];
    const uint32_t sbase = smem_u32(sm);

    const int tid = threadIdx.x, warp = tid >> 5, lane = tid & 31;
    const int wm = warp >> 1, wn = warp & 1;
    const int bx = blockIdx.x;
    const int qt = bx & 31, h = (bx >> 5) & 7, b = bx >> 8;

    const __half* qbh = qh + (size_t)(b * 4096 + qt * 128) * INNER + h * 64;
    const __half* kbh = kvh + (size_t)(b * MCTX) * KVDIM + h * 64;

    #pragma unroll
    for (int i = 0; i < 4; i++) {
        int idx = tid + i * 256;
        int r = idx >> 3, cc = idx & 7;
        *(uint4*)(sm + AQ_H + SWZ(r * 128 + cc * 16)) =
            *(const uint4*)(qbh + (size_t)r * INNER + cc * 8);
    }

    #pragma unroll
    for (int i = 0; i < 4; i++) {
        int idx = tid + i * 256;
        int r = idx >> 3, cc = idx & 7;
        uint32_t so = SWZ(r * 128 + cc * 16);
        size_t g = (size_t)r * KVDIM + cc * 8;
        CP_ASYNC(sbase + ASTG(0) +     0 + so, kbh + g);
        CP_ASYNC(sbase + ASTG(0) + 16384 + so, kbh + INNER + g);
    }
    CP_COMMIT();

    const int a_row = (lane & 15), a_cb = (lane >> 4) * 16;
    const int b_row = (lane & 7) + (lane >> 4) * 8, b_cb = ((lane >> 3) & 1) * 16;
    const int v_row = (lane & 7) + ((lane >> 3) & 1) * 8, v_cb = (lane >> 4) * 16;

    float o[2][8][4] = {};
    float lp[2][2] = {};

    for (int it = 0; it < 16; it++) {
        if (it < 15) {
            const uint32_t st = sbase + ASTG((it + 1) & 1);
            #pragma unroll
            for (int i = 0; i < 4; i++) {
                int idx = tid + i * 256;
                int r = idx >> 3, cc = idx & 7;
                uint32_t so = SWZ(r * 128 + cc * 16);
                size_t g = (size_t)((it + 1) * 128 + r) * KVDIM + cc * 8;
                CP_ASYNC(st +     0 + so, kbh + g);
                CP_ASYNC(st + 16384 + so, kbh + INNER + g);
            }
            CP_COMMIT();
            CP_WAIT(1);
        } else {
            CP_WAIT(0);
        }
        __syncthreads();

        const uint32_t kh_s = sbase + ASTG(it & 1);
        const uint32_t vh_s = kh_s + 16384;

        // ---- S = Qh Kh^T ----
        float s[2][8][4] = {};
        #pragma unroll
        for (int ks = 0; ks < 4; ks++) {
            uint32_t ah2[2][4], bh2[8][2];
            #pragma unroll
            for (int mt = 0; mt < 2; mt++) {
                int row = wm * 32 + mt * 16 + a_row;
                ldsm4(ah2[mt][0], ah2[mt][1], ah2[mt][2], ah2[mt][3],
                      sbase + AQ_H + SWZ(row * 128 + ks * 32 + a_cb));
            }
            #pragma unroll
            for (int np = 0; np < 4; np++) {
                int row = wn * 64 + np * 16 + b_row;
                uint32_t r0, r1, r2, r3;
                ldsm4(r0, r1, r2, r3, kh_s + SWZ(row * 128 + ks * 32 + b_cb));
                bh2[np*2][0] = r0; bh2[np*2][1] = r1;
                bh2[np*2+1][0] = r2; bh2[np*2+1][1] = r3;
            }
            #pragma unroll
            for (int mt = 0; mt < 2; mt++)
                #pragma unroll
                for (int nt = 0; nt < 8; nt++)
                    mma16816(s[mt][nt], ah2[mt], bh2[nt][0], bh2[nt][1]);
        }

        // ---- P = exp2(S) in fp16x2 (half the MUFU ops); l in fp32 ----
        uint32_t pa[2][4][4];
        #pragma unroll
        for (int mt = 0; mt < 2; mt++)
            #pragma unroll
            for (int ks2 = 0; ks2 < 4; ks2++)
                #pragma unroll
                for (int jj = 0; jj < 2; jj++) {
                    float* sv = s[mt][2 * ks2 + jj];
                    uint32_t h01 = ex2_h2(packh(sv[0], sv[1]));
                    uint32_t h23 = ex2_h2(packh(sv[2], sv[3]));
                    pa[mt][ks2][jj * 2]     = h01;
                    pa[mt][ks2][jj * 2 + 1] = h23;
                    float2 f01 = __half22float2(*(__half2*)&h01);
                    float2 f23 = __half22float2(*(__half2*)&h23);
                    lp[mt][0] += f01.x + f01.y;
                    lp[mt][1] += f23.x + f23.y;
                }

        // ---- O += Ph Vh ----
        #pragma unroll
        for (int ks2 = 0; ks2 < 4; ks2++) {
            const int key0 = wn * 64 + ks2 * 16;
            uint32_t bh2[8][2];
            #pragma unroll
            for (int D = 0; D < 4; D++) {
                uint32_t so = SWZ((key0 + v_row) * 128 + D * 32 + v_cb);
                uint32_t r0, r1, r2, r3;
                ldsm4t(r0, r1, r2, r3, vh_s + so);
                bh2[2*D][0] = r0; bh2[2*D][1] = r1;
                bh2[2*D+1][0] = r2; bh2[2*D+1][1] = r3;
            }
            #pragma unroll
            for (int mt = 0; mt < 2; mt++)
                #pragma unroll
                for (int dt = 0; dt < 8; dt++)
                    mma16816(o[mt][dt], pa[mt][ks2], bh2[dt][0], bh2[dt][1]);
        }
        __syncthreads();
    }

    // ---- l reduce ----
    float* lbuf = (float*)(sm + ALBUF);
    #pragma unroll
    for (int mt = 0; mt < 2; mt++)
        #pragma unroll
        for (int rr = 0; rr < 2; rr++) {
            float v = lp[mt][rr];
            v += __shfl_xor_sync(0xFFFFFFFF, v, 1);
            v += __shfl_xor_sync(0xFFFFFFFF, v, 2);
            if ((lane & 3) == 0)
                lbuf[wn * 128 + wm * 32 + mt * 16 + rr * 8 + (lane >> 2)] = v;
        }
    __syncthreads();

    // ---- O reduce across wn via smem ----
    float* obuf = (float*)sm;
    if (wn == 1) {
        #pragma unroll
        for (int mt = 0; mt < 2; mt++) {
            int r0 = wm * 32 + mt * 16 + (lane >> 2);
            #pragma unroll
            for (int dt = 0; dt < 8; dt++) {
                int col = dt * 8 + (lane & 3) * 2;
                *(float2*)(obuf + r0 * 64 + col) = make_float2(o[mt][dt][0], o[mt][dt][1]);
                *(float2*)(obuf + (r0 + 8) * 64 + col) = make_float2(o[mt][dt][2], o[mt][dt][3]);
            }
        }
    }
    __syncthreads();
    if (wn == 0) {
        #pragma unroll
        for (int mt = 0; mt < 2; mt++) {
            int r0 = wm * 32 + mt * 16 + (lane >> 2);
            int r1 = r0 + 8;
            float inv0 = 1.0f / (lbuf[r0] + lbuf[128 + r0]);
            float inv1 = 1.0f / (lbuf[r1] + lbuf[128 + r1]);
            #pragma unroll
            for (int dt = 0; dt < 8; dt++) {
                int col = dt * 8 + (lane & 3) * 2;
                float2 p0 = *(float2*)(obuf + r0 * 64 + col);
                float2 p1 = *(float2*)(obuf + r1 * 64 + col);
                float v0 = (o[mt][dt][0] + p0.x) * inv0;
                float v1 = (o[mt][dt][1] + p0.y) * inv0;
                float v2 = (o[mt][dt][2] + p1.x) * inv1;
                float v3 = (o[mt][dt][3] + p1.y) * inv1;
                uint32_t h01 = packh(v0, v1), h23 = packh(v2, v3);
                __half2 H01 = *(__half2*)&h01, H23 = *(__half2*)&h23;
                uint32_t l01 = packh(v0 - __low2float(H01), v1 - __high2float(H01));
                uint32_t l23 = packh(v2 - __low2float(H23), v3 - __high2float(H23));
                size_t g0 = (size_t)(b * 4096 + qt * 128 + r0) * INNER + h * 64 + col;
                size_t g1 = (size_t)(b * 4096 + qt * 128 + r1) * INNER + h * 64 + col;
                *(uint32_t*)(aoh + g0) = h01;
                *(uint32_t*)(aoh + g1) = h23;
                *(uint32_t*)(aol + g0) = l01;
                *(uint32_t*)(aol + g1) = l23;
            }
        }
    }
}

// ---------------------------------------------------------------------------
extern "C" void kernel_launch(void* const* d_in, const int* in_sizes, int n_in,
                              void* d_out, int out_size)
{
    const float* x   = (const float*)d_in[0];
    const float* ctx = (const float*)d_in[1];
    const float* Wq  = (const float*)d_in[2];
    const float* Wkv = (const float*)d_in[3];
    const float* Wo  = (const float*)d_in[4];
    const float* bo  = (const float*)d_in[5];
    float* out = (float*)d_out;

    __half *xh, *ch, *wqh, *wkh, *woh, *qh2, *kvh, *aoh, *aol;
    cudaGetSymbolAddress((void**)&xh,  g_xh);
    cudaGetSymbolAddress((void**)&ch,  g_ch);
    cudaGetSymbolAddress((void**)&wqh, g_wqh);
    cudaGetSymbolAddress((void**)&wkh, g_wkh);
    cudaGetSymbolAddress((void**)&woh, g_woh);
    cudaGetSymbolAddress((void**)&qh2, g_qh);
    cudaGetSymbolAddress((void**)&kvh, g_kvh);
    cudaGetSymbolAddress((void**)&aoh, g_aoh);
    cudaGetSymbolAddress((void**)&aol, g_aol);

    cudaFuncSetAttribute(mm_gemm_qkv, cudaFuncAttributeMaxDynamicSharedMemorySize, G_SM_TOTAL);
    cudaFuncSetAttribute(mm_gemm_o,   cudaFuncAttributeMaxDynamicSharedMemorySize, G_SM_TOTAL);
    cudaFuncSetAttribute(mm_attn,     cudaFuncAttributeMaxDynamicSharedMemorySize, A_SM_TOTAL);

    // x feeds only Wq: pre-scale by log2(e)/8 so attn softmax is exp2(S)
    const float QSCALE = 0.18033688011112042f;
    int n1 = NROWS * QDIM / 4, n2 = CROWS * QDIM / 4;
    split_inputs<<<(n1 + n2 + 255) / 256, 256>>>(
        (const float4*)x, (const float4*)ctx, (uint2*)xh, (uint2*)ch, n1, n2, QSCALE);
    split_transpose3<<<dim3(KVDIM / 32, QDIM / 64, 3), 256>>>(
        Wq, Wkv, Wo, wqh, wkh, woh);

    mm_gemm_qkv<<<512, 256, G_SM_TOTAL>>>(xh, wqh, qh2, ch, wkh, kvh);

    mm_attn<<<512, 256, A_SM_TOTAL>>>(qh2, kvh, aoh, aol);

    mm_gemm_o<<<dim3(INNER / 128, NROWS / 128), 256, G_SM_TOTAL>>>(
        aoh, aol, woh, out, bo);
}

// round 14
// speedup vs baseline: 1.0564x; 1.0564x over previous
#include <cuda_runtime.h>
#include <cuda_fp16.h>
#include <cstdint>
#include <cstddef>

#define NROWS 8192
#define CROWS 4096
#define QDIM  512
#define INNER 512
#define KVDIM 1024
#define MCTX  2048

// ---------------- static scratch (fp16) --------------------------------------
__device__ __align__(256) __half g_xh [NROWS * QDIM];
__device__ __align__(256) __half g_ch [CROWS * QDIM];
__device__ __align__(256) __half g_wqh[INNER * QDIM];
__device__ __align__(256) __half g_wkh[KVDIM * QDIM];
__device__ __align__(256) __half g_woh[INNER * INNER];
__device__ __align__(256) __half g_qh [NROWS * INNER];
__device__ __align__(256) __half g_kvh[CROWS * KVDIM];
__device__ __align__(256) __half g_aoh[NROWS * INNER], g_aol[NROWS * INNER];

// ---------------- helpers ----------------------------------------------------
#define SWZ(off) ((off) ^ (((off) >> 3) & 0x70))

static __device__ __forceinline__ uint32_t smem_u32(const void* p) {
    uint32_t a;
    asm("{ .reg .u64 t; cvta.to.shared.u64 t, %1; cvt.u32.u64 %0, t; }"
        : "=r"(a) : "l"(p));
    return a;
}
static __device__ __forceinline__ void ldsm4(uint32_t& r0, uint32_t& r1,
                                             uint32_t& r2, uint32_t& r3, uint32_t a) {
    asm volatile("ldmatrix.sync.aligned.m8n8.x4.shared.b16 {%0,%1,%2,%3}, [%4];"
                 : "=r"(r0), "=r"(r1), "=r"(r2), "=r"(r3) : "r"(a));
}
static __device__ __forceinline__ void ldsm4t(uint32_t& r0, uint32_t& r1,
                                              uint32_t& r2, uint32_t& r3, uint32_t a) {
    asm volatile("ldmatrix.sync.aligned.m8n8.x4.trans.shared.b16 {%0,%1,%2,%3}, [%4];"
                 : "=r"(r0), "=r"(r1), "=r"(r2), "=r"(r3) : "r"(a));
}
static __device__ __forceinline__ void mma16816(float* c, const uint32_t* a,
                                                uint32_t b0, uint32_t b1) {
    asm volatile("mma.sync.aligned.m16n8k16.row.col.f32.f16.f16.f32 "
                 "{%0,%1,%2,%3}, {%4,%5,%6,%7}, {%8,%9}, {%0,%1,%2,%3};"
                 : "+f"(c[0]), "+f"(c[1]), "+f"(c[2]), "+f"(c[3])
                 : "r"(a[0]), "r"(a[1]), "r"(a[2]), "r"(a[3]), "r"(b0), "r"(b1));
}
static __device__ __forceinline__ uint32_t packh(float a, float b) {
    __half2 t = __floats2half2_rn(a, b);
    return *(uint32_t*)&t;
}
static __device__ __forceinline__ uint32_t ex2_h2(uint32_t h2) {
    asm("ex2.approx.f16x2 %0, %0;" : "+r"(h2));
    return h2;
}
#define CP_ASYNC(dst, src) \
    asm volatile("cp.async.cg.shared.global [%0], [%1], 16;" \
                 :: "r"(dst), "l"(src) : "memory")
#define CP_COMMIT() asm volatile("cp.async.commit_group;" ::: "memory")
#define CP_WAIT(n)  asm volatile("cp.async.wait_group %0;" :: "n"(n) : "memory")

// ---------------- conversion kernels ------------------------------------------
__global__ void split_inputs(const float4* __restrict__ x, const float4* __restrict__ c,
                             uint2* __restrict__ xh, uint2* __restrict__ ch,
                             int n1, int n2, float qscale) {
    int i = blockIdx.x * 256 + threadIdx.x;
    const float4* in;
    uint2* oh;
    float scale;
    if (i < n1) { in = x; oh = xh; scale = qscale; }
    else {
        i -= n1;
        if (i >= n2) return;
        in = c; oh = ch; scale = 1.0f;
    }
    float4 v = in[i];
    oh[i] = make_uint2(packh(v.x * scale, v.y * scale),
                       packh(v.z * scale, v.w * scale));
}

__global__ __launch_bounds__(256)
void split_transpose3(const float* __restrict__ w0, const float* __restrict__ w1,
                      const float* __restrict__ w2,
                      __half* __restrict__ oh0, __half* __restrict__ oh1,
                      __half* __restrict__ oh2) {
    const int z = blockIdx.z;
    const float* in = (z == 0) ? w0 : (z == 1) ? w1 : w2;
    __half* oh = (z == 0) ? oh0 : (z == 1) ? oh1 : oh2;
    const int N = (z == 1) ? KVDIM : INNER;
    const int K = QDIM;
    const int n0 = blockIdx.x * 32;
    if (n0 >= N) return;

    __shared__ float t[64][33];
    const int tid = threadIdx.x, tx = tid & 31, ty = tid >> 5;
    const int k0 = blockIdx.y * 64;
    #pragma unroll
    for (int r = ty; r < 64; r += 8)
        t[r][tx] = in[(size_t)(k0 + r) * N + n0 + tx];
    __syncthreads();
    #pragma unroll
    for (int r = ty; r < 32; r += 8) {
        int n = n0 + r;
        *(uint32_t*)(oh + (size_t)n * K + k0 + tx * 2) =
            packh(t[tx * 2][r], t[tx * 2 + 1][r]);
    }
}

// ---------------- HMMA GEMM core (device body, unchanged) ---------------------
#define GSTG(s) ((s) * 49152)
#define G_SM_TOTAL 98304

template <int MODE, int TERMS>
static __device__ __forceinline__
void gemm_body(const __half* __restrict__ ah, const __half* __restrict__ al,
               const __half* __restrict__ bth,
               __half* __restrict__ coh, __half* __restrict__ col_,
               float* __restrict__ cf, const float* __restrict__ bias,
               int M, int N, int K, int bm, int bn, char* sm)
{
    const uint32_t sbase = smem_u32(sm);
    const int tid = threadIdx.x, warp = tid >> 5, lane = tid & 31;
    const int wm = warp >> 2, wn = warp & 3;

    float c[4][4][4] = {};

    const int a_row = (lane & 15), a_cb = (lane >> 4) * 16;
    const int b_row = (lane & 7) + (lane >> 4) * 8, b_cb = ((lane >> 3) & 1) * 16;

    const int NCH = K >> 6;

    #pragma unroll
    for (int p = 0; p < 2; p++) {
        const uint32_t st = sbase + GSTG(p);
        #pragma unroll
        for (int i = 0; i < 4; i++) {
            int idx = tid + i * 256;
            int r = idx >> 3, cc = idx & 7;
            uint32_t off = SWZ(r * 128 + cc * 16);
            size_t ga = (size_t)(bm + r) * K + p * 64 + cc * 8;
            size_t gb = (size_t)(bn + r) * K + p * 64 + cc * 8;
            CP_ASYNC(st + 0 + off, ah + ga);
            if (TERMS == 2) CP_ASYNC(st + 16384 + off, al + ga);
            CP_ASYNC(st + 32768 + off, bth + gb);
        }
        CP_COMMIT();
    }

    for (int it = 0; it < NCH; it++) {
        if (it + 1 < NCH) CP_WAIT(1); else CP_WAIT(0);
        __syncthreads();

        const uint32_t ah_s = sbase + GSTG(it & 1);
        const uint32_t al_s = ah_s + 16384;
        const uint32_t bh_s = ah_s + 32768;

        #pragma unroll
        for (int ks = 0; ks < 4; ks++) {
            uint32_t afh[4][4], afl[4][4], bfr[4][2];
            #pragma unroll
            for (int mt = 0; mt < 4; mt++) {
                int row = wm * 64 + mt * 16 + a_row;
                uint32_t so = SWZ(row * 128 + ks * 32 + a_cb);
                ldsm4(afh[mt][0], afh[mt][1], afh[mt][2], afh[mt][3], ah_s + so);
                if (TERMS == 2)
                    ldsm4(afl[mt][0], afl[mt][1], afl[mt][2], afl[mt][3], al_s + so);
            }
            #pragma unroll
            for (int np = 0; np < 2; np++) {
                int row = wn * 32 + np * 16 + b_row;
                uint32_t r0, r1, r2, r3;
                ldsm4(r0, r1, r2, r3, bh_s + SWZ(row * 128 + ks * 32 + b_cb));
                bfr[np*2][0] = r0; bfr[np*2][1] = r1;
                bfr[np*2+1][0] = r2; bfr[np*2+1][1] = r3;
            }
            #pragma unroll
            for (int mt = 0; mt < 4; mt++)
                #pragma unroll
                for (int nt = 0; nt < 4; nt++) {
                    mma16816(c[mt][nt], afh[mt], bfr[nt][0], bfr[nt][1]);
                    if (TERMS == 2)
                        mma16816(c[mt][nt], afl[mt], bfr[nt][0], bfr[nt][1]);
                }
        }
        __syncthreads();

        if (it + 2 < NCH) {
            const uint32_t st = sbase + GSTG(it & 1);
            const int k0 = (it + 2) << 6;
            #pragma unroll
            for (int i = 0; i < 4; i++) {
                int idx = tid + i * 256;
                int r = idx >> 3, cc = idx & 7;
                uint32_t off = SWZ(r * 128 + cc * 16);
                size_t ga = (size_t)(bm + r) * K + k0 + cc * 8;
                size_t gb = (size_t)(bn + r) * K + k0 + cc * 8;
                CP_ASYNC(st + 0 + off, ah + ga);
                if (TERMS == 2) CP_ASYNC(st + 16384 + off, al + ga);
                CP_ASYNC(st + 32768 + off, bth + gb);
            }
            CP_COMMIT();
        }
    }

    #pragma unroll
    for (int mt = 0; mt < 4; mt++) {
        int row0 = bm + wm * 64 + mt * 16 + (lane >> 2);
        #pragma unroll
        for (int nt = 0; nt < 4; nt++) {
            int col = bn + wn * 32 + nt * 8 + (lane & 3) * 2;
            float v0 = c[mt][nt][0], v1 = c[mt][nt][1];
            float v2 = c[mt][nt][2], v3 = c[mt][nt][3];
            if (MODE == 1) {
                float b0 = bias[col], b1 = bias[col + 1];
                *(float2*)(cf + (size_t)row0 * N + col)       = make_float2(v0 + b0, v1 + b1);
                *(float2*)(cf + (size_t)(row0 + 8) * N + col) = make_float2(v2 + b0, v3 + b1);
            } else {
                uint32_t h01 = packh(v0, v1), h23 = packh(v2, v3);
                *(uint32_t*)(coh  + (size_t)row0 * N + col)       = h01;
                *(uint32_t*)(coh  + (size_t)(row0 + 8) * N + col) = h23;
                if (MODE == 0) {
                    __half2 H01 = *(__half2*)&h01, H23 = *(__half2*)&h23;
                    uint32_t l01 = packh(v0 - __low2float(H01), v1 - __high2float(H01));
                    uint32_t l23 = packh(v2 - __low2float(H23), v3 - __high2float(H23));
                    *(uint32_t*)(col_ + (size_t)row0 * N + col)       = l01;
                    *(uint32_t*)(col_ + (size_t)(row0 + 8) * N + col) = l23;
                }
            }
        }
    }
}

__global__ __launch_bounds__(256, 2)
void mm_gemm_qkv(const __half* __restrict__ xh, const __half* __restrict__ wqh,
                 __half* __restrict__ qh,
                 const __half* __restrict__ ch, const __half* __restrict__ wkh,
                 __half* __restrict__ kvh)
{
    extern __shared__ __align__(128) char sm[];
    const int bid = blockIdx.x;
    if (bid < 256) {
        int bn = (bid & 3) * 128, bm = (bid >> 2) * 128;
        gemm_body<2, 1>(xh, nullptr, wqh, qh, nullptr, nullptr, nullptr,
                        NROWS, INNER, QDIM, bm, bn, sm);
    } else {
        int t = bid - 256;
        int bn = (t & 7) * 128, bm = (t >> 3) * 128;
        gemm_body<2, 1>(ch, nullptr, wkh, kvh, nullptr, nullptr, nullptr,
                        CROWS, KVDIM, QDIM, bm, bn, sm);
    }
}

__global__ __launch_bounds__(256, 2)
void mm_gemm_o(const __half* __restrict__ aoh, const __half* __restrict__ aol,
               const __half* __restrict__ woh, float* __restrict__ out,
               const float* __restrict__ bias)
{
    extern __shared__ __align__(128) char sm[];
    gemm_body<1, 2>(aoh, aol, woh, nullptr, nullptr, out, bias,
                    NROWS, INNER, INNER, blockIdx.y * 128, blockIdx.x * 128, sm);
}

// ---------------- HMMA flash attention: occ-2 redesign -------------------------
// 128-q blocks, 256 threads, 8 warps. Each warp owns 16 q-rows x ALL keys
// (no key split -> no cross-warp O/l reduction). Keys processed 64 at a time
// (2 sub-passes per 128-chunk) to keep live s/pa small. Q fragments hoisted
// to registers (16 regs). Target: <=128 regs -> 2 CTAs/SM (16 warps).
#define AQ_H 0
#define ASTG(s) (16384 + (s) * 32768)   // +0 KH (16K), +16384 VH (16K)
#define A_SM_TOTAL 81920

__global__ __launch_bounds__(256, 2)
void mm_attn(const __half* __restrict__ qh, const __half* __restrict__ kvh,
             __half* __restrict__ aoh, __half* __restrict__ aol)
{
    extern __shared__ __align__(128) char sm[];
    const uint32_t sbase = smem_u32(sm);

    const int tid = threadIdx.x, warp = tid >> 5, lane = tid & 31;
    const int bx = blockIdx.x;
    const int qt = bx & 31, h = (bx >> 5) & 7, b = bx >> 8;

    const __half* qbh = qh + (size_t)(b * 4096 + qt * 128) * INNER + h * 64;
    const __half* kbh = kvh + (size_t)(b * MCTX) * KVDIM + h * 64;

    // Q tile -> smem (cooperative)
    #pragma unroll
    for (int i = 0; i < 4; i++) {
        int idx = tid + i * 256;
        int r = idx >> 3, cc = idx & 7;
        *(uint4*)(sm + AQ_H + SWZ(r * 128 + cc * 16)) =
            *(const uint4*)(qbh + (size_t)r * INNER + cc * 8);
    }

    // prefetch chunk 0 (K hi + V hi)
    #pragma unroll
    for (int i = 0; i < 4; i++) {
        int idx = tid + i * 256;
        int r = idx >> 3, cc = idx & 7;
        uint32_t so = SWZ(r * 128 + cc * 16);
        size_t g = (size_t)r * KVDIM + cc * 8;
        CP_ASYNC(sbase + ASTG(0) +     0 + so, kbh + g);
        CP_ASYNC(sbase + ASTG(0) + 16384 + so, kbh + INNER + g);
    }
    CP_COMMIT();

    const int a_row = (lane & 15), a_cb = (lane >> 4) * 16;
    const int b_row = (lane & 7) + (lane >> 4) * 8, b_cb = ((lane >> 3) & 1) * 16;
    const int v_row = (lane & 7) + ((lane >> 3) & 1) * 8, v_cb = (lane >> 4) * 16;

    // hoist Q fragments: 1 m-tile (16 rows) x 4 k-steps = 16 regs
    __syncthreads();
    uint32_t qf[4][4];
    #pragma unroll
    for (int ks = 0; ks < 4; ks++)
        ldsm4(qf[ks][0], qf[ks][1], qf[ks][2], qf[ks][3],
              sbase + AQ_H + SWZ((warp * 16 + a_row) * 128 + ks * 32 + a_cb));

    float o[8][4] = {};
    float lp[2] = {};

    for (int it = 0; it < 16; it++) {
        if (it < 15) {
            const uint32_t st = sbase + ASTG((it + 1) & 1);
            #pragma unroll
            for (int i = 0; i < 4; i++) {
                int idx = tid + i * 256;
                int r = idx >> 3, cc = idx & 7;
                uint32_t so = SWZ(r * 128 + cc * 16);
                size_t g = (size_t)((it + 1) * 128 + r) * KVDIM + cc * 8;
                CP_ASYNC(st +     0 + so, kbh + g);
                CP_ASYNC(st + 16384 + so, kbh + INNER + g);
            }
            CP_COMMIT();
            CP_WAIT(1);
        } else {
            CP_WAIT(0);
        }
        __syncthreads();

        const uint32_t kh_s = sbase + ASTG(it & 1);
        const uint32_t vh_s = kh_s + 16384;

        #pragma unroll
        for (int h2 = 0; h2 < 2; h2++) {
            // ---- S = Qh Kh^T over 64 keys ----
            float s[8][4] = {};
            #pragma unroll
            for (int ks = 0; ks < 4; ks++) {
                uint32_t bh2[8][2];
                #pragma unroll
                for (int np = 0; np < 4; np++) {
                    int row = h2 * 64 + np * 16 + b_row;
                    uint32_t r0, r1, r2, r3;
                    ldsm4(r0, r1, r2, r3, kh_s + SWZ(row * 128 + ks * 32 + b_cb));
                    bh2[np*2][0] = r0; bh2[np*2][1] = r1;
                    bh2[np*2+1][0] = r2; bh2[np*2+1][1] = r3;
                }
                #pragma unroll
                for (int nt = 0; nt < 8; nt++)
                    mma16816(s[nt], qf[ks], bh2[nt][0], bh2[nt][1]);
            }

            // ---- P = exp2(S) fp16x2; l fp32 ----
            uint32_t pa[4][4];
            #pragma unroll
            for (int ks2 = 0; ks2 < 4; ks2++)
                #pragma unroll
                for (int jj = 0; jj < 2; jj++) {
                    float* sv = s[2 * ks2 + jj];
                    uint32_t h01 = ex2_h2(packh(sv[0], sv[1]));
                    uint32_t h23 = ex2_h2(packh(sv[2], sv[3]));
                    pa[ks2][jj * 2]     = h01;
                    pa[ks2][jj * 2 + 1] = h23;
                    float2 f01 = __half22float2(*(__half2*)&h01);
                    float2 f23 = __half22float2(*(__half2*)&h23);
                    lp[0] += f01.x + f01.y;
                    lp[1] += f23.x + f23.y;
                }

            // ---- O += Ph Vh ----
            #pragma unroll
            for (int ks2 = 0; ks2 < 4; ks2++) {
                const int key0 = h2 * 64 + ks2 * 16;
                uint32_t bh2[8][2];
                #pragma unroll
                for (int D = 0; D < 4; D++) {
                    uint32_t so = SWZ((key0 + v_row) * 128 + D * 32 + v_cb);
                    uint32_t r0, r1, r2, r3;
                    ldsm4t(r0, r1, r2, r3, vh_s + so);
                    bh2[2*D][0] = r0; bh2[2*D][1] = r1;
                    bh2[2*D+1][0] = r2; bh2[2*D+1][1] = r3;
                }
                #pragma unroll
                for (int dt = 0; dt < 8; dt++)
                    mma16816(o[dt], pa[ks2], bh2[dt][0], bh2[dt][1]);
            }
        }
        __syncthreads();
    }

    // ---- epilogue: quad all-reduce of l, scale, write hi/lo (no smem) ----
    #pragma unroll
    for (int rr = 0; rr < 2; rr++) {
        lp[rr] += __shfl_xor_sync(0xFFFFFFFF, lp[rr], 1);
        lp[rr] += __shfl_xor_sync(0xFFFFFFFF, lp[rr], 2);
    }
    float inv0 = 1.0f / lp[0], inv1 = 1.0f / lp[1];

    int r0 = warp * 16 + (lane >> 2);
    int r1 = r0 + 8;
    size_t g0 = (size_t)(b * 4096 + qt * 128 + r0) * INNER + h * 64;
    size_t g1 = (size_t)(b * 4096 + qt * 128 + r1) * INNER + h * 64;
    #pragma unroll
    for (int dt = 0; dt < 8; dt++) {
        int col = dt * 8 + (lane & 3) * 2;
        float v0 = o[dt][0] * inv0, v1 = o[dt][1] * inv0;
        float v2 = o[dt][2] * inv1, v3 = o[dt][3] * inv1;
        uint32_t h01 = packh(v0, v1), h23 = packh(v2, v3);
        __half2 H01 = *(__half2*)&h01, H23 = *(__half2*)&h23;
        uint32_t l01 = packh(v0 - __low2float(H01), v1 - __high2float(H01));
        uint32_t l23 = packh(v2 - __low2float(H23), v3 - __high2float(H23));
        *(uint32_t*)(aoh + g0 + col) = h01;
        *(uint32_t*)(aoh + g1 + col) = h23;
        *(uint32_t*)(aol + g0 + col) = l01;
        *(uint32_t*)(aol + g1 + col) = l23;
    }
}

// ---------------------------------------------------------------------------
extern "C" void kernel_launch(void* const* d_in, const int* in_sizes, int n_in,
                              void* d_out, int out_size)
{
    const float* x   = (const float*)d_in[0];
    const float* ctx = (const float*)d_in[1];
    const float* Wq  = (const float*)d_in[2];
    const float* Wkv = (const float*)d_in[3];
    const float* Wo  = (const float*)d_in[4];
    const float* bo  = (const float*)d_in[5];
    float* out = (float*)d_out;

    __half *xh, *ch, *wqh, *wkh, *woh, *qh2, *kvh, *aoh, *aol;
    cudaGetSymbolAddress((void**)&xh,  g_xh);
    cudaGetSymbolAddress((void**)&ch,  g_ch);
    cudaGetSymbolAddress((void**)&wqh, g_wqh);
    cudaGetSymbolAddress((void**)&wkh, g_wkh);
    cudaGetSymbolAddress((void**)&woh, g_woh);
    cudaGetSymbolAddress((void**)&qh2, g_qh);
    cudaGetSymbolAddress((void**)&kvh, g_kvh);
    cudaGetSymbolAddress((void**)&aoh, g_aoh);
    cudaGetSymbolAddress((void**)&aol, g_aol);

    cudaFuncSetAttribute(mm_gemm_qkv, cudaFuncAttributeMaxDynamicSharedMemorySize, G_SM_TOTAL);
    cudaFuncSetAttribute(mm_gemm_o,   cudaFuncAttributeMaxDynamicSharedMemorySize, G_SM_TOTAL);
    cudaFuncSetAttribute(mm_attn,     cudaFuncAttributeMaxDynamicSharedMemorySize, A_SM_TOTAL);

    // x feeds only Wq: pre-scale by log2(e)/8 so attn softmax is exp2(S)
    const float QSCALE = 0.18033688011112042f;
    int n1 = NROWS * QDIM / 4, n2 = CROWS * QDIM / 4;
    split_inputs<<<(n1 + n2 + 255) / 256, 256>>>(
        (const float4*)x, (const float4*)ctx, (uint2*)xh, (uint2*)ch, n1, n2, QSCALE);
    split_transpose3<<<dim3(KVDIM / 32, QDIM / 64, 3), 256>>>(
        Wq, Wkv, Wo, wqh, wkh, woh);

    mm_gemm_qkv<<<512, 256, G_SM_TOTAL>>>(xh, wqh, qh2, ch, wkh, kvh);

    mm_attn<<<512, 256, A_SM_TOTAL>>>(qh2, kvh, aoh, aol);

    mm_gemm_o<<<dim3(INNER / 128, NROWS / 128), 256, G_SM_TOTAL>>>(
        aoh, aol, woh, out, bo);
}

// round 15
// speedup vs baseline: 1.0737x; 1.0164x over previous
#include <cuda_runtime.h>
#include <cuda_fp16.h>
#include <cstdint>
#include <cstddef>

#define NROWS 8192
#define CROWS 4096
#define QDIM  512
#define INNER 512
#define KVDIM 1024
#define MCTX  2048

// ---------------- static scratch (fp16) --------------------------------------
__device__ __align__(256) __half g_xh [NROWS * QDIM];
__device__ __align__(256) __half g_ch [CROWS * QDIM];
__device__ __align__(256) __half g_wqh[INNER * QDIM];
__device__ __align__(256) __half g_wkh[KVDIM * QDIM];
__device__ __align__(256) __half g_woh[INNER * INNER];
__device__ __align__(256) __half g_qh [NROWS * INNER];
__device__ __align__(256) __half g_kvh[CROWS * KVDIM];
__device__ __align__(256) __half g_aoh[NROWS * INNER], g_aol[NROWS * INNER];

// ---------------- helpers ----------------------------------------------------
#define SWZ(off) ((off) ^ (((off) >> 3) & 0x70))

static __device__ __forceinline__ uint32_t smem_u32(const void* p) {
    uint32_t a;
    asm("{ .reg .u64 t; cvta.to.shared.u64 t, %1; cvt.u32.u64 %0, t; }"
        : "=r"(a) : "l"(p));
    return a;
}
static __device__ __forceinline__ void ldsm4(uint32_t& r0, uint32_t& r1,
                                             uint32_t& r2, uint32_t& r3, uint32_t a) {
    asm volatile("ldmatrix.sync.aligned.m8n8.x4.shared.b16 {%0,%1,%2,%3}, [%4];"
                 : "=r"(r0), "=r"(r1), "=r"(r2), "=r"(r3) : "r"(a));
}
static __device__ __forceinline__ void ldsm4t(uint32_t& r0, uint32_t& r1,
                                              uint32_t& r2, uint32_t& r3, uint32_t a) {
    asm volatile("ldmatrix.sync.aligned.m8n8.x4.trans.shared.b16 {%0,%1,%2,%3}, [%4];"
                 : "=r"(r0), "=r"(r1), "=r"(r2), "=r"(r3) : "r"(a));
}
static __device__ __forceinline__ void mma16816(float* c, const uint32_t* a,
                                                uint32_t b0, uint32_t b1) {
    asm volatile("mma.sync.aligned.m16n8k16.row.col.f32.f16.f16.f32 "
                 "{%0,%1,%2,%3}, {%4,%5,%6,%7}, {%8,%9}, {%0,%1,%2,%3};"
                 : "+f"(c[0]), "+f"(c[1]), "+f"(c[2]), "+f"(c[3])
                 : "r"(a[0]), "r"(a[1]), "r"(a[2]), "r"(a[3]), "r"(b0), "r"(b1));
}
static __device__ __forceinline__ uint32_t packh(float a, float b) {
    __half2 t = __floats2half2_rn(a, b);
    return *(uint32_t*)&t;
}
static __device__ __forceinline__ uint32_t ex2_h2(uint32_t h2) {
    asm("ex2.approx.f16x2 %0, %0;" : "+r"(h2));
    return h2;
}
#define CP_ASYNC(dst, src) \
    asm volatile("cp.async.cg.shared.global [%0], [%1], 16;" \
                 :: "r"(dst), "l"(src) : "memory")
#define CP_COMMIT() asm volatile("cp.async.commit_group;" ::: "memory")
#define CP_WAIT(n)  asm volatile("cp.async.wait_group %0;" :: "n"(n) : "memory")

// ---------------- conversion kernels ------------------------------------------
__global__ void split_inputs(const float4* __restrict__ x, const float4* __restrict__ c,
                             uint2* __restrict__ xh, uint2* __restrict__ ch,
                             int n1, int n2, float qscale) {
    int i = blockIdx.x * 256 + threadIdx.x;
    const float4* in;
    uint2* oh;
    float scale;
    if (i < n1) { in = x; oh = xh; scale = qscale; }
    else {
        i -= n1;
        if (i >= n2) return;
        in = c; oh = ch; scale = 1.0f;
    }
    float4 v = in[i];
    oh[i] = make_uint2(packh(v.x * scale, v.y * scale),
                       packh(v.z * scale, v.w * scale));
}

__global__ __launch_bounds__(256)
void split_transpose3(const float* __restrict__ w0, const float* __restrict__ w1,
                      const float* __restrict__ w2,
                      __half* __restrict__ oh0, __half* __restrict__ oh1,
                      __half* __restrict__ oh2) {
    const int z = blockIdx.z;
    const float* in = (z == 0) ? w0 : (z == 1) ? w1 : w2;
    __half* oh = (z == 0) ? oh0 : (z == 1) ? oh1 : oh2;
    const int N = (z == 1) ? KVDIM : INNER;
    const int K = QDIM;
    const int n0 = blockIdx.x * 32;
    if (n0 >= N) return;

    __shared__ float t[64][33];
    const int tid = threadIdx.x, tx = tid & 31, ty = tid >> 5;
    const int k0 = blockIdx.y * 64;
    #pragma unroll
    for (int r = ty; r < 64; r += 8)
        t[r][tx] = in[(size_t)(k0 + r) * N + n0 + tx];
    __syncthreads();
    #pragma unroll
    for (int r = ty; r < 32; r += 8) {
        int n = n0 + r;
        *(uint32_t*)(oh + (size_t)n * K + k0 + tx * 2) =
            packh(t[tx * 2][r], t[tx * 2 + 1][r]);
    }
}

// ---------------- HMMA GEMM core (device body, unchanged) ---------------------
#define GSTG(s) ((s) * 49152)
#define G_SM_TOTAL 98304

template <int MODE, int TERMS>
static __device__ __forceinline__
void gemm_body(const __half* __restrict__ ah, const __half* __restrict__ al,
               const __half* __restrict__ bth,
               __half* __restrict__ coh, __half* __restrict__ col_,
               float* __restrict__ cf, const float* __restrict__ bias,
               int M, int N, int K, int bm, int bn, char* sm)
{
    const uint32_t sbase = smem_u32(sm);
    const int tid = threadIdx.x, warp = tid >> 5, lane = tid & 31;
    const int wm = warp >> 2, wn = warp & 3;

    float c[4][4][4] = {};

    const int a_row = (lane & 15), a_cb = (lane >> 4) * 16;
    const int b_row = (lane & 7) + (lane >> 4) * 8, b_cb = ((lane >> 3) & 1) * 16;

    const int NCH = K >> 6;

    #pragma unroll
    for (int p = 0; p < 2; p++) {
        const uint32_t st = sbase + GSTG(p);
        #pragma unroll
        for (int i = 0; i < 4; i++) {
            int idx = tid + i * 256;
            int r = idx >> 3, cc = idx & 7;
            uint32_t off = SWZ(r * 128 + cc * 16);
            size_t ga = (size_t)(bm + r) * K + p * 64 + cc * 8;
            size_t gb = (size_t)(bn + r) * K + p * 64 + cc * 8;
            CP_ASYNC(st + 0 + off, ah + ga);
            if (TERMS == 2) CP_ASYNC(st + 16384 + off, al + ga);
            CP_ASYNC(st + 32768 + off, bth + gb);
        }
        CP_COMMIT();
    }

    for (int it = 0; it < NCH; it++) {
        if (it + 1 < NCH) CP_WAIT(1); else CP_WAIT(0);
        __syncthreads();

        const uint32_t ah_s = sbase + GSTG(it & 1);
        const uint32_t al_s = ah_s + 16384;
        const uint32_t bh_s = ah_s + 32768;

        #pragma unroll
        for (int ks = 0; ks < 4; ks++) {
            uint32_t afh[4][4], afl[4][4], bfr[4][2];
            #pragma unroll
            for (int mt = 0; mt < 4; mt++) {
                int row = wm * 64 + mt * 16 + a_row;
                uint32_t so = SWZ(row * 128 + ks * 32 + a_cb);
                ldsm4(afh[mt][0], afh[mt][1], afh[mt][2], afh[mt][3], ah_s + so);
                if (TERMS == 2)
                    ldsm4(afl[mt][0], afl[mt][1], afl[mt][2], afl[mt][3], al_s + so);
            }
            #pragma unroll
            for (int np = 0; np < 2; np++) {
                int row = wn * 32 + np * 16 + b_row;
                uint32_t r0, r1, r2, r3;
                ldsm4(r0, r1, r2, r3, bh_s + SWZ(row * 128 + ks * 32 + b_cb));
                bfr[np*2][0] = r0; bfr[np*2][1] = r1;
                bfr[np*2+1][0] = r2; bfr[np*2+1][1] = r3;
            }
            #pragma unroll
            for (int mt = 0; mt < 4; mt++)
                #pragma unroll
                for (int nt = 0; nt < 4; nt++) {
                    mma16816(c[mt][nt], afh[mt], bfr[nt][0], bfr[nt][1]);
                    if (TERMS == 2)
                        mma16816(c[mt][nt], afl[mt], bfr[nt][0], bfr[nt][1]);
                }
        }
        __syncthreads();

        if (it + 2 < NCH) {
            const uint32_t st = sbase + GSTG(it & 1);
            const int k0 = (it + 2) << 6;
            #pragma unroll
            for (int i = 0; i < 4; i++) {
                int idx = tid + i * 256;
                int r = idx >> 3, cc = idx & 7;
                uint32_t off = SWZ(r * 128 + cc * 16);
                size_t ga = (size_t)(bm + r) * K + k0 + cc * 8;
                size_t gb = (size_t)(bn + r) * K + k0 + cc * 8;
                CP_ASYNC(st + 0 + off, ah + ga);
                if (TERMS == 2) CP_ASYNC(st + 16384 + off, al + ga);
                CP_ASYNC(st + 32768 + off, bth + gb);
            }
            CP_COMMIT();
        }
    }

    #pragma unroll
    for (int mt = 0; mt < 4; mt++) {
        int row0 = bm + wm * 64 + mt * 16 + (lane >> 2);
        #pragma unroll
        for (int nt = 0; nt < 4; nt++) {
            int col = bn + wn * 32 + nt * 8 + (lane & 3) * 2;
            float v0 = c[mt][nt][0], v1 = c[mt][nt][1];
            float v2 = c[mt][nt][2], v3 = c[mt][nt][3];
            if (MODE == 1) {
                float b0 = bias[col], b1 = bias[col + 1];
                *(float2*)(cf + (size_t)row0 * N + col)       = make_float2(v0 + b0, v1 + b1);
                *(float2*)(cf + (size_t)(row0 + 8) * N + col) = make_float2(v2 + b0, v3 + b1);
            } else {
                uint32_t h01 = packh(v0, v1), h23 = packh(v2, v3);
                *(uint32_t*)(coh  + (size_t)row0 * N + col)       = h01;
                *(uint32_t*)(coh  + (size_t)(row0 + 8) * N + col) = h23;
                if (MODE == 0) {
                    __half2 H01 = *(__half2*)&h01, H23 = *(__half2*)&h23;
                    uint32_t l01 = packh(v0 - __low2float(H01), v1 - __high2float(H01));
                    uint32_t l23 = packh(v2 - __low2float(H23), v3 - __high2float(H23));
                    *(uint32_t*)(col_ + (size_t)row0 * N + col)       = l01;
                    *(uint32_t*)(col_ + (size_t)(row0 + 8) * N + col) = l23;
                }
            }
        }
    }
}

__global__ __launch_bounds__(256, 2)
void mm_gemm_qkv(const __half* __restrict__ xh, const __half* __restrict__ wqh,
                 __half* __restrict__ qh,
                 const __half* __restrict__ ch, const __half* __restrict__ wkh,
                 __half* __restrict__ kvh)
{
    extern __shared__ __align__(128) char sm[];
    const int bid = blockIdx.x;
    if (bid < 256) {
        int bn = (bid & 3) * 128, bm = (bid >> 2) * 128;
        gemm_body<2, 1>(xh, nullptr, wqh, qh, nullptr, nullptr, nullptr,
                        NROWS, INNER, QDIM, bm, bn, sm);
    } else {
        int t = bid - 256;
        int bn = (t & 7) * 128, bm = (t >> 3) * 128;
        gemm_body<2, 1>(ch, nullptr, wkh, kvh, nullptr, nullptr, nullptr,
                        CROWS, KVDIM, QDIM, bm, bn, sm);
    }
}

__global__ __launch_bounds__(256, 2)
void mm_gemm_o(const __half* __restrict__ aoh, const __half* __restrict__ aol,
               const __half* __restrict__ woh, float* __restrict__ out,
               const float* __restrict__ bias)
{
    extern __shared__ __align__(128) char sm[];
    gemm_body<1, 2>(aoh, aol, woh, nullptr, nullptr, out, bias,
                    NROWS, INNER, INNER, blockIdx.y * 128, blockIdx.x * 128, sm);
}

// ---------------- HMMA flash attention: 64-q blocks, 4 row x 2 key warps -------
// 8 warps: wm=warp>>1 (16 q-rows each of 64), wn=warp&1 (64-key half).
// K/V fragment duplication 4x (vs 8x in R14) -> L1 pressure halves.
// Q frags in registers; occ 2 (16 warps/SM). Cross-wn O/l reduce via smem.
#define AQ_H 0
#define ASTG(s) (8192 + (s) * 32768)    // +0 KH (16K), +16384 VH (16K)
#define ALBUF 73728                      // 2 x 64 floats
#define A_SM_TOTAL 74240

__global__ __launch_bounds__(256, 2)
void mm_attn(const __half* __restrict__ qh, const __half* __restrict__ kvh,
             __half* __restrict__ aoh, __half* __restrict__ aol)
{
    extern __shared__ __align__(128) char sm[];
    const uint32_t sbase = smem_u32(sm);

    const int tid = threadIdx.x, warp = tid >> 5, lane = tid & 31;
    const int wm = warp >> 1, wn = warp & 1;
    const int bx = blockIdx.x;
    const int qt = bx & 63, h = (bx >> 6) & 7, b = bx >> 9;

    const __half* qbh = qh + (size_t)(b * 4096 + qt * 64) * INNER + h * 64;
    const __half* kbh = kvh + (size_t)(b * MCTX) * KVDIM + h * 64;

    // Q tile -> smem (64 rows x 128B)
    #pragma unroll
    for (int i = 0; i < 2; i++) {
        int idx = tid + i * 256;
        int r = idx >> 3, cc = idx & 7;
        *(uint4*)(sm + AQ_H + SWZ(r * 128 + cc * 16)) =
            *(const uint4*)(qbh + (size_t)r * INNER + cc * 8);
    }

    // prefetch chunk 0 (K hi + V hi, 128 keys)
    #pragma unroll
    for (int i = 0; i < 4; i++) {
        int idx = tid + i * 256;
        int r = idx >> 3, cc = idx & 7;
        uint32_t so = SWZ(r * 128 + cc * 16);
        size_t g = (size_t)r * KVDIM + cc * 8;
        CP_ASYNC(sbase + ASTG(0) +     0 + so, kbh + g);
        CP_ASYNC(sbase + ASTG(0) + 16384 + so, kbh + INNER + g);
    }
    CP_COMMIT();

    const int a_row = (lane & 15), a_cb = (lane >> 4) * 16;
    const int b_row = (lane & 7) + (lane >> 4) * 8, b_cb = ((lane >> 3) & 1) * 16;
    const int v_row = (lane & 7) + ((lane >> 3) & 1) * 8, v_cb = (lane >> 4) * 16;

    // hoist Q fragments: 16 rows x 4 k-steps = 16 regs
    __syncthreads();
    uint32_t qf[4][4];
    #pragma unroll
    for (int ks = 0; ks < 4; ks++)
        ldsm4(qf[ks][0], qf[ks][1], qf[ks][2], qf[ks][3],
              sbase + AQ_H + SWZ((wm * 16 + a_row) * 128 + ks * 32 + a_cb));

    float o[8][4] = {};
    float lp[2] = {};

    for (int it = 0; it < 16; it++) {
        if (it < 15) {
            const uint32_t st = sbase + ASTG((it + 1) & 1);
            #pragma unroll
            for (int i = 0; i < 4; i++) {
                int idx = tid + i * 256;
                int r = idx >> 3, cc = idx & 7;
                uint32_t so = SWZ(r * 128 + cc * 16);
                size_t g = (size_t)((it + 1) * 128 + r) * KVDIM + cc * 8;
                CP_ASYNC(st +     0 + so, kbh + g);
                CP_ASYNC(st + 16384 + so, kbh + INNER + g);
            }
            CP_COMMIT();
            CP_WAIT(1);
        } else {
            CP_WAIT(0);
        }
        __syncthreads();

        const uint32_t kh_s = sbase + ASTG(it & 1);
        const uint32_t vh_s = kh_s + 16384;

        // ---- S = Qh Kh^T over this warp's 64-key half ----
        float s[8][4] = {};
        #pragma unroll
        for (int ks = 0; ks < 4; ks++) {
            uint32_t bh2[8][2];
            #pragma unroll
            for (int np = 0; np < 4; np++) {
                int row = wn * 64 + np * 16 + b_row;
                uint32_t r0, r1, r2, r3;
                ldsm4(r0, r1, r2, r3, kh_s + SWZ(row * 128 + ks * 32 + b_cb));
                bh2[np*2][0] = r0; bh2[np*2][1] = r1;
                bh2[np*2+1][0] = r2; bh2[np*2+1][1] = r3;
            }
            #pragma unroll
            for (int nt = 0; nt < 8; nt++)
                mma16816(s[nt], qf[ks], bh2[nt][0], bh2[nt][1]);
        }

        // ---- P = exp2(S) fp16x2; l fp32 ----
        uint32_t pa[4][4];
        #pragma unroll
        for (int ks2 = 0; ks2 < 4; ks2++)
            #pragma unroll
            for (int jj = 0; jj < 2; jj++) {
                float* sv = s[2 * ks2 + jj];
                uint32_t h01 = ex2_h2(packh(sv[0], sv[1]));
                uint32_t h23 = ex2_h2(packh(sv[2], sv[3]));
                pa[ks2][jj * 2]     = h01;
                pa[ks2][jj * 2 + 1] = h23;
                float2 f01 = __half22float2(*(__half2*)&h01);
                float2 f23 = __half22float2(*(__half2*)&h23);
                lp[0] += f01.x + f01.y;
                lp[1] += f23.x + f23.y;
            }

        // ---- O += Ph Vh (this key half) ----
        #pragma unroll
        for (int ks2 = 0; ks2 < 4; ks2++) {
            const int key0 = wn * 64 + ks2 * 16;
            uint32_t bh2[8][2];
            #pragma unroll
            for (int D = 0; D < 4; D++) {
                uint32_t so = SWZ((key0 + v_row) * 128 + D * 32 + v_cb);
                uint32_t r0, r1, r2, r3;
                ldsm4t(r0, r1, r2, r3, vh_s + so);
                bh2[2*D][0] = r0; bh2[2*D][1] = r1;
                bh2[2*D+1][0] = r2; bh2[2*D+1][1] = r3;
            }
            #pragma unroll
            for (int dt = 0; dt < 8; dt++)
                mma16816(o[dt], pa[ks2], bh2[dt][0], bh2[dt][1]);
        }
        __syncthreads();
    }

    // ---- l: quad reduce, stash per key-half ----
    float* lbuf = (float*)(sm + ALBUF);
    #pragma unroll
    for (int rr = 0; rr < 2; rr++) {
        float v = lp[rr];
        v += __shfl_xor_sync(0xFFFFFFFF, v, 1);
        v += __shfl_xor_sync(0xFFFFFFFF, v, 2);
        if ((lane & 3) == 0)
            lbuf[wn * 64 + wm * 16 + rr * 8 + (lane >> 2)] = v;
    }
    __syncthreads();

    // ---- O reduce across wn via smem (reuse stage 0: 16KB) ----
    float* obuf = (float*)(sm + ASTG(0));
    if (wn == 1) {
        int r0 = wm * 16 + (lane >> 2);
        #pragma unroll
        for (int dt = 0; dt < 8; dt++) {
            int col = dt * 8 + (lane & 3) * 2;
            *(float2*)(obuf + r0 * 64 + col)       = make_float2(o[dt][0], o[dt][1]);
            *(float2*)(obuf + (r0 + 8) * 64 + col) = make_float2(o[dt][2], o[dt][3]);
        }
    }
    __syncthreads();
    if (wn == 0) {
        int r0 = wm * 16 + (lane >> 2);
        int r1 = r0 + 8;
        float inv0 = 1.0f / (lbuf[r0] + lbuf[64 + r0]);
        float inv1 = 1.0f / (lbuf[r1] + lbuf[64 + r1]);
        size_t g0 = (size_t)(b * 4096 + qt * 64 + r0) * INNER + h * 64;
        size_t g1 = (size_t)(b * 4096 + qt * 64 + r1) * INNER + h * 64;
        #pragma unroll
        for (int dt = 0; dt < 8; dt++) {
            int col = dt * 8 + (lane & 3) * 2;
            float2 p0 = *(float2*)(obuf + r0 * 64 + col);
            float2 p1 = *(float2*)(obuf + r1 * 64 + col);
            float v0 = (o[dt][0] + p0.x) * inv0;
            float v1 = (o[dt][1] + p0.y) * inv0;
            float v2 = (o[dt][2] + p1.x) * inv1;
            float v3 = (o[dt][3] + p1.y) * inv1;
            uint32_t h01 = packh(v0, v1), h23 = packh(v2, v3);
            __half2 H01 = *(__half2*)&h01, H23 = *(__half2*)&h23;
            uint32_t l01 = packh(v0 - __low2float(H01), v1 - __high2float(H01));
            uint32_t l23 = packh(v2 - __low2float(H23), v3 - __high2float(H23));
            *(uint32_t*)(aoh + g0 + col) = h01;
            *(uint32_t*)(aoh + g1 + col) = h23;
            *(uint32_t*)(aol + g0 + col) = l01;
            *(uint32_t*)(aol + g1 + col) = l23;
        }
    }
}

// ---------------------------------------------------------------------------
extern "C" void kernel_launch(void* const* d_in, const int* in_sizes, int n_in,
                              void* d_out, int out_size)
{
    const float* x   = (const float*)d_in[0];
    const float* ctx = (const float*)d_in[1];
    const float* Wq  = (const float*)d_in[2];
    const float* Wkv = (const float*)d_in[3];
    const float* Wo  = (const float*)d_in[4];
    const float* bo  = (const float*)d_in[5];
    float* out = (float*)d_out;

    __half *xh, *ch, *wqh, *wkh, *woh, *qh2, *kvh, *aoh, *aol;
    cudaGetSymbolAddress((void**)&xh,  g_xh);
    cudaGetSymbolAddress((void**)&ch,  g_ch);
    cudaGetSymbolAddress((void**)&wqh, g_wqh);
    cudaGetSymbolAddress((void**)&wkh, g_wkh);
    cudaGetSymbolAddress((void**)&woh, g_woh);
    cudaGetSymbolAddress((void**)&qh2, g_qh);
    cudaGetSymbolAddress((void**)&kvh, g_kvh);
    cudaGetSymbolAddress((void**)&aoh, g_aoh);
    cudaGetSymbolAddress((void**)&aol, g_aol);

    cudaFuncSetAttribute(mm_gemm_qkv, cudaFuncAttributeMaxDynamicSharedMemorySize, G_SM_TOTAL);
    cudaFuncSetAttribute(mm_gemm_o,   cudaFuncAttributeMaxDynamicSharedMemorySize, G_SM_TOTAL);
    cudaFuncSetAttribute(mm_attn,     cudaFuncAttributeMaxDynamicSharedMemorySize, A_SM_TOTAL);

    // x feeds only Wq: pre-scale by log2(e)/8 so attn softmax is exp2(S)
    const float QSCALE = 0.18033688011112042f;
    int n1 = NROWS * QDIM / 4, n2 = CROWS * QDIM / 4;
    split_inputs<<<(n1 + n2 + 255) / 256, 256>>>(
        (const float4*)x, (const float4*)ctx, (uint2*)xh, (uint2*)ch, n1, n2, QSCALE);
    split_transpose3<<<dim3(KVDIM / 32, QDIM / 64, 3), 256>>>(
        Wq, Wkv, Wo, wqh, wkh, woh);

    mm_gemm_qkv<<<512, 256, G_SM_TOTAL>>>(xh, wqh, qh2, ch, wkh, kvh);

    mm_attn<<<1024, 256, A_SM_TOTAL>>>(qh2, kvh, aoh, aol);

    mm_gemm_o<<<dim3(INNER / 128, NROWS / 128), 256, G_SM_TOTAL>>>(
        aoh, aol, woh, out, bo);
}

// round 16
// speedup vs baseline: 1.1552x; 1.0758x over previous
#include <cuda_runtime.h>
#include <cuda_fp16.h>
#include <cstdint>
#include <cstddef>

#define NROWS 8192
#define CROWS 4096
#define QDIM  512
#define INNER 512
#define KVDIM 1024
#define MCTX  2048

// ---------------- static scratch (fp16) --------------------------------------
__device__ __align__(256) __half g_xh [NROWS * QDIM];
__device__ __align__(256) __half g_ch [CROWS * QDIM];
__device__ __align__(256) __half g_wqh[INNER * QDIM];
__device__ __align__(256) __half g_wkh[KVDIM * QDIM];
__device__ __align__(256) __half g_woh[INNER * INNER];
__device__ __align__(256) __half g_qh [NROWS * INNER];
__device__ __align__(256) __half g_kvh[CROWS * KVDIM];
__device__ __align__(256) __half g_aoh[NROWS * INNER];

// ---------------- helpers ----------------------------------------------------
#define SWZ(off) ((off) ^ (((off) >> 3) & 0x70))

static __device__ __forceinline__ uint32_t smem_u32(const void* p) {
    uint32_t a;
    asm("{ .reg .u64 t; cvta.to.shared.u64 t, %1; cvt.u32.u64 %0, t; }"
        : "=r"(a) : "l"(p));
    return a;
}
static __device__ __forceinline__ void ldsm4(uint32_t& r0, uint32_t& r1,
                                             uint32_t& r2, uint32_t& r3, uint32_t a) {
    asm volatile("ldmatrix.sync.aligned.m8n8.x4.shared.b16 {%0,%1,%2,%3}, [%4];"
                 : "=r"(r0), "=r"(r1), "=r"(r2), "=r"(r3) : "r"(a));
}
static __device__ __forceinline__ void ldsm4t(uint32_t& r0, uint32_t& r1,
                                              uint32_t& r2, uint32_t& r3, uint32_t a) {
    asm volatile("ldmatrix.sync.aligned.m8n8.x4.trans.shared.b16 {%0,%1,%2,%3}, [%4];"
                 : "=r"(r0), "=r"(r1), "=r"(r2), "=r"(r3) : "r"(a));
}
static __device__ __forceinline__ void mma16816(float* c, const uint32_t* a,
                                                uint32_t b0, uint32_t b1) {
    asm volatile("mma.sync.aligned.m16n8k16.row.col.f32.f16.f16.f32 "
                 "{%0,%1,%2,%3}, {%4,%5,%6,%7}, {%8,%9}, {%0,%1,%2,%3};"
                 : "+f"(c[0]), "+f"(c[1]), "+f"(c[2]), "+f"(c[3])
                 : "r"(a[0]), "r"(a[1]), "r"(a[2]), "r"(a[3]), "r"(b0), "r"(b1));
}
static __device__ __forceinline__ uint32_t packh(float a, float b) {
    __half2 t = __floats2half2_rn(a, b);
    return *(uint32_t*)&t;
}
static __device__ __forceinline__ uint32_t ex2_h2(uint32_t h2) {
    asm("ex2.approx.f16x2 %0, %0;" : "+r"(h2));
    return h2;
}
#define CP_ASYNC(dst, src) \
    asm volatile("cp.async.cg.shared.global [%0], [%1], 16;" \
                 :: "r"(dst), "l"(src) : "memory")
#define CP_COMMIT() asm volatile("cp.async.commit_group;" ::: "memory")
#define CP_WAIT(n)  asm volatile("cp.async.wait_group %0;" :: "n"(n) : "memory")

// ---------------- conversion kernels ------------------------------------------
__global__ void split_inputs(const float4* __restrict__ x, const float4* __restrict__ c,
                             uint2* __restrict__ xh, uint2* __restrict__ ch,
                             int n1, int n2, float qscale) {
    int i = blockIdx.x * 256 + threadIdx.x;
    const float4* in;
    uint2* oh;
    float scale;
    if (i < n1) { in = x; oh = xh; scale = qscale; }
    else {
        i -= n1;
        if (i >= n2) return;
        in = c; oh = ch; scale = 1.0f;
    }
    float4 v = in[i];
    oh[i] = make_uint2(packh(v.x * scale, v.y * scale),
                       packh(v.z * scale, v.w * scale));
}

__global__ __launch_bounds__(256)
void split_transpose3(const float* __restrict__ w0, const float* __restrict__ w1,
                      const float* __restrict__ w2,
                      __half* __restrict__ oh0, __half* __restrict__ oh1,
                      __half* __restrict__ oh2) {
    const int z = blockIdx.z;
    const float* in = (z == 0) ? w0 : (z == 1) ? w1 : w2;
    __half* oh = (z == 0) ? oh0 : (z == 1) ? oh1 : oh2;
    const int N = (z == 1) ? KVDIM : INNER;
    const int K = QDIM;
    const int n0 = blockIdx.x * 32;
    if (n0 >= N) return;

    __shared__ float t[64][33];
    const int tid = threadIdx.x, tx = tid & 31, ty = tid >> 5;
    const int k0 = blockIdx.y * 64;
    #pragma unroll
    for (int r = ty; r < 64; r += 8)
        t[r][tx] = in[(size_t)(k0 + r) * N + n0 + tx];
    __syncthreads();
    #pragma unroll
    for (int r = ty; r < 32; r += 8) {
        int n = n0 + r;
        *(uint32_t*)(oh + (size_t)n * K + k0 + tx * 2) =
            packh(t[tx * 2][r], t[tx * 2 + 1][r]);
    }
}

// ---------------- HMMA GEMM core (device body) --------------------------------
#define GSTG(s) ((s) * 49152)
#define G_SM_TOTAL 98304

template <int MODE, int TERMS>   // MODE 1: fp32+bias; MODE 2: fp16 hi out
static __device__ __forceinline__
void gemm_body(const __half* __restrict__ ah, const __half* __restrict__ al,
               const __half* __restrict__ bth,
               __half* __restrict__ coh,
               float* __restrict__ cf, const float* __restrict__ bias,
               int M, int N, int K, int bm, int bn, char* sm)
{
    const uint32_t sbase = smem_u32(sm);
    const int tid = threadIdx.x, warp = tid >> 5, lane = tid & 31;
    const int wm = warp >> 2, wn = warp & 3;

    float c[4][4][4] = {};

    const int a_row = (lane & 15), a_cb = (lane >> 4) * 16;
    const int b_row = (lane & 7) + (lane >> 4) * 8, b_cb = ((lane >> 3) & 1) * 16;

    const int NCH = K >> 6;

    #pragma unroll
    for (int p = 0; p < 2; p++) {
        const uint32_t st = sbase + GSTG(p);
        #pragma unroll
        for (int i = 0; i < 4; i++) {
            int idx = tid + i * 256;
            int r = idx >> 3, cc = idx & 7;
            uint32_t off = SWZ(r * 128 + cc * 16);
            size_t ga = (size_t)(bm + r) * K + p * 64 + cc * 8;
            size_t gb = (size_t)(bn + r) * K + p * 64 + cc * 8;
            CP_ASYNC(st + 0 + off, ah + ga);
            if (TERMS == 2) CP_ASYNC(st + 16384 + off, al + ga);
            CP_ASYNC(st + 32768 + off, bth + gb);
        }
        CP_COMMIT();
    }

    for (int it = 0; it < NCH; it++) {
        if (it + 1 < NCH) CP_WAIT(1); else CP_WAIT(0);
        __syncthreads();

        const uint32_t ah_s = sbase + GSTG(it & 1);
        const uint32_t al_s = ah_s + 16384;
        const uint32_t bh_s = ah_s + 32768;

        #pragma unroll
        for (int ks = 0; ks < 4; ks++) {
            uint32_t afh[4][4], afl[4][4], bfr[4][2];
            #pragma unroll
            for (int mt = 0; mt < 4; mt++) {
                int row = wm * 64 + mt * 16 + a_row;
                uint32_t so = SWZ(row * 128 + ks * 32 + a_cb);
                ldsm4(afh[mt][0], afh[mt][1], afh[mt][2], afh[mt][3], ah_s + so);
                if (TERMS == 2)
                    ldsm4(afl[mt][0], afl[mt][1], afl[mt][2], afl[mt][3], al_s + so);
            }
            #pragma unroll
            for (int np = 0; np < 2; np++) {
                int row = wn * 32 + np * 16 + b_row;
                uint32_t r0, r1, r2, r3;
                ldsm4(r0, r1, r2, r3, bh_s + SWZ(row * 128 + ks * 32 + b_cb));
                bfr[np*2][0] = r0; bfr[np*2][1] = r1;
                bfr[np*2+1][0] = r2; bfr[np*2+1][1] = r3;
            }
            #pragma unroll
            for (int mt = 0; mt < 4; mt++)
                #pragma unroll
                for (int nt = 0; nt < 4; nt++) {
                    mma16816(c[mt][nt], afh[mt], bfr[nt][0], bfr[nt][1]);
                    if (TERMS == 2)
                        mma16816(c[mt][nt], afl[mt], bfr[nt][0], bfr[nt][1]);
                }
        }
        __syncthreads();

        if (it + 2 < NCH) {
            const uint32_t st = sbase + GSTG(it & 1);
            const int k0 = (it + 2) << 6;
            #pragma unroll
            for (int i = 0; i < 4; i++) {
                int idx = tid + i * 256;
                int r = idx >> 3, cc = idx & 7;
                uint32_t off = SWZ(r * 128 + cc * 16);
                size_t ga = (size_t)(bm + r) * K + k0 + cc * 8;
                size_t gb = (size_t)(bn + r) * K + k0 + cc * 8;
                CP_ASYNC(st + 0 + off, ah + ga);
                if (TERMS == 2) CP_ASYNC(st + 16384 + off, al + ga);
                CP_ASYNC(st + 32768 + off, bth + gb);
            }
            CP_COMMIT();
        }
    }

    #pragma unroll
    for (int mt = 0; mt < 4; mt++) {
        int row0 = bm + wm * 64 + mt * 16 + (lane >> 2);
        #pragma unroll
        for (int nt = 0; nt < 4; nt++) {
            int col = bn + wn * 32 + nt * 8 + (lane & 3) * 2;
            float v0 = c[mt][nt][0], v1 = c[mt][nt][1];
            float v2 = c[mt][nt][2], v3 = c[mt][nt][3];
            if (MODE == 1) {
                float b0 = bias[col], b1 = bias[col + 1];
                *(float2*)(cf + (size_t)row0 * N + col)       = make_float2(v0 + b0, v1 + b1);
                *(float2*)(cf + (size_t)(row0 + 8) * N + col) = make_float2(v2 + b0, v3 + b1);
            } else {
                *(uint32_t*)(coh + (size_t)row0 * N + col)       = packh(v0, v1);
                *(uint32_t*)(coh + (size_t)(row0 + 8) * N + col) = packh(v2, v3);
            }
        }
    }
}

__global__ __launch_bounds__(256, 2)
void mm_gemm_qkv(const __half* __restrict__ xh, const __half* __restrict__ wqh,
                 __half* __restrict__ qh,
                 const __half* __restrict__ ch, const __half* __restrict__ wkh,
                 __half* __restrict__ kvh)
{
    extern __shared__ __align__(128) char sm[];
    const int bid = blockIdx.x;
    if (bid < 256) {
        int bn = (bid & 3) * 128, bm = (bid >> 2) * 128;
        gemm_body<2, 1>(xh, nullptr, wqh, qh, nullptr, nullptr,
                        NROWS, INNER, QDIM, bm, bn, sm);
    } else {
        int t = bid - 256;
        int bn = (t & 7) * 128, bm = (t >> 3) * 128;
        gemm_body<2, 1>(ch, nullptr, wkh, kvh, nullptr, nullptr,
                        CROWS, KVDIM, QDIM, bm, bn, sm);
    }
}

// O projection: 1-term (attn-out hi only), fp32 + bias
__global__ __launch_bounds__(256, 2)
void mm_gemm_o(const __half* __restrict__ aoh, const __half* __restrict__ woh,
               float* __restrict__ out, const float* __restrict__ bias)
{
    extern __shared__ __align__(128) char sm[];
    gemm_body<1, 1>(aoh, nullptr, woh, nullptr, out, bias,
                    NROWS, INNER, INNER, blockIdx.y * 128, blockIdx.x * 128, sm);
}

// ---------------- HMMA flash attention: 64-q blocks, 3-stage, 1 sync/chunk ----
// 8 warps: wm=warp>>1 (16 q-rows of 64), wn=warp&1 (64-key half).
// Stages: chunk it -> stage it%3. Refill chunk it+2 at top of iter it (that
// stage was last read at it-1; the sync proves all warps are past it).
#define AQ_H 0
#define ASTG(s) (8192 + (s) * 32768)    // +0 KH (16K), +16384 VH (16K)
#define ALBUF (8192 + 3 * 32768)         // 106496
#define A_SM_TOTAL 107008

__global__ __launch_bounds__(256, 2)
void mm_attn(const __half* __restrict__ qh, const __half* __restrict__ kvh,
             __half* __restrict__ aoh)
{
    extern __shared__ __align__(128) char sm[];
    const uint32_t sbase = smem_u32(sm);

    const int tid = threadIdx.x, warp = tid >> 5, lane = tid & 31;
    const int wm = warp >> 1, wn = warp & 1;
    const int bx = blockIdx.x;
    const int qt = bx & 63, h = (bx >> 6) & 7, b = bx >> 9;

    const __half* qbh = qh + (size_t)(b * 4096 + qt * 64) * INNER + h * 64;
    const __half* kbh = kvh + (size_t)(b * MCTX) * KVDIM + h * 64;

    // Q tile -> smem (64 rows x 128B)
    #pragma unroll
    for (int i = 0; i < 2; i++) {
        int idx = tid + i * 256;
        int r = idx >> 3, cc = idx & 7;
        *(uint4*)(sm + AQ_H + SWZ(r * 128 + cc * 16)) =
            *(const uint4*)(qbh + (size_t)r * INNER + cc * 8);
    }

    // prefetch chunks 0 and 1
    #pragma unroll
    for (int p = 0; p < 2; p++) {
        const uint32_t st = sbase + ASTG(p);
        #pragma unroll
        for (int i = 0; i < 4; i++) {
            int idx = tid + i * 256;
            int r = idx >> 3, cc = idx & 7;
            uint32_t so = SWZ(r * 128 + cc * 16);
            size_t g = (size_t)(p * 128 + r) * KVDIM + cc * 8;
            CP_ASYNC(st +     0 + so, kbh + g);
            CP_ASYNC(st + 16384 + so, kbh + INNER + g);
        }
        CP_COMMIT();
    }

    const int a_row = (lane & 15), a_cb = (lane >> 4) * 16;
    const int b_row = (lane & 7) + (lane >> 4) * 8, b_cb = ((lane >> 3) & 1) * 16;
    const int v_row = (lane & 7) + ((lane >> 3) & 1) * 8, v_cb = (lane >> 4) * 16;

    // hoist Q fragments: 16 rows x 4 k-steps = 16 regs
    __syncthreads();
    uint32_t qf[4][4];
    #pragma unroll
    for (int ks = 0; ks < 4; ks++)
        ldsm4(qf[ks][0], qf[ks][1], qf[ks][2], qf[ks][3],
              sbase + AQ_H + SWZ((wm * 16 + a_row) * 128 + ks * 32 + a_cb));

    float o[8][4] = {};
    float lp[2] = {};

    int stg = 0;   // stage of current chunk
    for (int it = 0; it < 16; it++) {
        if (it + 1 < 16) CP_WAIT(1); else CP_WAIT(0);
        __syncthreads();   // all warps past chunk it-1 reads; chunk it ready

        // refill chunk it+2 into stage (stg+2)%3 (last read at it-1)
        if (it + 2 < 16) {
            int s2 = stg + 2; if (s2 >= 3) s2 -= 3;
            const uint32_t st = sbase + ASTG(s2);
            #pragma unroll
            for (int i = 0; i < 4; i++) {
                int idx = tid + i * 256;
                int r = idx >> 3, cc = idx & 7;
                uint32_t so = SWZ(r * 128 + cc * 16);
                size_t g = (size_t)((it + 2) * 128 + r) * KVDIM + cc * 8;
                CP_ASYNC(st +     0 + so, kbh + g);
                CP_ASYNC(st + 16384 + so, kbh + INNER + g);
            }
            CP_COMMIT();
        }

        const uint32_t kh_s = sbase + ASTG(stg);
        const uint32_t vh_s = kh_s + 16384;

        // ---- S = Qh Kh^T over this warp's 64-key half ----
        float s[8][4] = {};
        #pragma unroll
        for (int ks = 0; ks < 4; ks++) {
            uint32_t bh2[8][2];
            #pragma unroll
            for (int np = 0; np < 4; np++) {
                int row = wn * 64 + np * 16 + b_row;
                uint32_t r0, r1, r2, r3;
                ldsm4(r0, r1, r2, r3, kh_s + SWZ(row * 128 + ks * 32 + b_cb));
                bh2[np*2][0] = r0; bh2[np*2][1] = r1;
                bh2[np*2+1][0] = r2; bh2[np*2+1][1] = r3;
            }
            #pragma unroll
            for (int nt = 0; nt < 8; nt++)
                mma16816(s[nt], qf[ks], bh2[nt][0], bh2[nt][1]);
        }

        // ---- P = exp2(S) fp16x2; l fp32 ----
        uint32_t pa[4][4];
        #pragma unroll
        for (int ks2 = 0; ks2 < 4; ks2++)
            #pragma unroll
            for (int jj = 0; jj < 2; jj++) {
                float* sv = s[2 * ks2 + jj];
                uint32_t h01 = ex2_h2(packh(sv[0], sv[1]));
                uint32_t h23 = ex2_h2(packh(sv[2], sv[3]));
                pa[ks2][jj * 2]     = h01;
                pa[ks2][jj * 2 + 1] = h23;
                float2 f01 = __half22float2(*(__half2*)&h01);
                float2 f23 = __half22float2(*(__half2*)&h23);
                lp[0] += f01.x + f01.y;
                lp[1] += f23.x + f23.y;
            }

        // ---- O += Ph Vh (this key half) ----
        #pragma unroll
        for (int ks2 = 0; ks2 < 4; ks2++) {
            const int key0 = wn * 64 + ks2 * 16;
            uint32_t bh2[8][2];
            #pragma unroll
            for (int D = 0; D < 4; D++) {
                uint32_t so = SWZ((key0 + v_row) * 128 + D * 32 + v_cb);
                uint32_t r0, r1, r2, r3;
                ldsm4t(r0, r1, r2, r3, vh_s + so);
                bh2[2*D][0] = r0; bh2[2*D][1] = r1;
                bh2[2*D+1][0] = r2; bh2[2*D+1][1] = r3;
            }
            #pragma unroll
            for (int dt = 0; dt < 8; dt++)
                mma16816(o[dt], pa[ks2], bh2[dt][0], bh2[dt][1]);
        }

        if (++stg >= 3) stg = 0;
    }
    __syncthreads();

    // ---- l: quad reduce, stash per key-half ----
    float* lbuf = (float*)(sm + ALBUF);
    #pragma unroll
    for (int rr = 0; rr < 2; rr++) {
        float v = lp[rr];
        v += __shfl_xor_sync(0xFFFFFFFF, v, 1);
        v += __shfl_xor_sync(0xFFFFFFFF, v, 2);
        if ((lane & 3) == 0)
            lbuf[wn * 64 + wm * 16 + rr * 8 + (lane >> 2)] = v;
    }
    __syncthreads();

    // ---- O reduce across wn via smem (reuse stage 0: 16KB) ----
    float* obuf = (float*)(sm + ASTG(0));
    if (wn == 1) {
        int r0 = wm * 16 + (lane >> 2);
        #pragma unroll
        for (int dt = 0; dt < 8; dt++) {
            int col = dt * 8 + (lane & 3) * 2;
            *(float2*)(obuf + r0 * 64 + col)       = make_float2(o[dt][0], o[dt][1]);
            *(float2*)(obuf + (r0 + 8) * 64 + col) = make_float2(o[dt][2], o[dt][3]);
        }
    }
    __syncthreads();
    if (wn == 0) {
        int r0 = wm * 16 + (lane >> 2);
        int r1 = r0 + 8;
        float inv0 = 1.0f / (lbuf[r0] + lbuf[64 + r0]);
        float inv1 = 1.0f / (lbuf[r1] + lbuf[64 + r1]);
        size_t g0 = (size_t)(b * 4096 + qt * 64 + r0) * INNER + h * 64;
        size_t g1 = (size_t)(b * 4096 + qt * 64 + r1) * INNER + h * 64;
        #pragma unroll
        for (int dt = 0; dt < 8; dt++) {
            int col = dt * 8 + (lane & 3) * 2;
            float2 p0 = *(float2*)(obuf + r0 * 64 + col);
            float2 p1 = *(float2*)(obuf + r1 * 64 + col);
            *(uint32_t*)(aoh + g0 + col) =
                packh((o[dt][0] + p0.x) * inv0, (o[dt][1] + p0.y) * inv0);
            *(uint32_t*)(aoh + g1 + col) =
                packh((o[dt][2] + p1.x) * inv1, (o[dt][3] + p1.y) * inv1);
        }
    }
}

// ---------------------------------------------------------------------------
extern "C" void kernel_launch(void* const* d_in, const int* in_sizes, int n_in,
                              void* d_out, int out_size)
{
    const float* x   = (const float*)d_in[0];
    const float* ctx = (const float*)d_in[1];
    const float* Wq  = (const float*)d_in[2];
    const float* Wkv = (const float*)d_in[3];
    const float* Wo  = (const float*)d_in[4];
    const float* bo  = (const float*)d_in[5];
    float* out = (float*)d_out;

    __half *xh, *ch, *wqh, *wkh, *woh, *qh2, *kvh, *aoh;
    cudaGetSymbolAddress((void**)&xh,  g_xh);
    cudaGetSymbolAddress((void**)&ch,  g_ch);
    cudaGetSymbolAddress((void**)&wqh, g_wqh);
    cudaGetSymbolAddress((void**)&wkh, g_wkh);
    cudaGetSymbolAddress((void**)&woh, g_woh);
    cudaGetSymbolAddress((void**)&qh2, g_qh);
    cudaGetSymbolAddress((void**)&kvh, g_kvh);
    cudaGetSymbolAddress((void**)&aoh, g_aoh);

    cudaFuncSetAttribute(mm_gemm_qkv, cudaFuncAttributeMaxDynamicSharedMemorySize, G_SM_TOTAL);
    cudaFuncSetAttribute(mm_gemm_o,   cudaFuncAttributeMaxDynamicSharedMemorySize, G_SM_TOTAL);
    cudaFuncSetAttribute(mm_attn,     cudaFuncAttributeMaxDynamicSharedMemorySize, A_SM_TOTAL);

    // x feeds only Wq: pre-scale by log2(e)/8 so attn softmax is exp2(S)
    const float QSCALE = 0.18033688011112042f;
    int n1 = NROWS * QDIM / 4, n2 = CROWS * QDIM / 4;
    split_inputs<<<(n1 + n2 + 255) / 256, 256>>>(
        (const float4*)x, (const float4*)ctx, (uint2*)xh, (uint2*)ch, n1, n2, QSCALE);
    split_transpose3<<<dim3(KVDIM / 32, QDIM / 64, 3), 256>>>(
        Wq, Wkv, Wo, wqh, wkh, woh);

    mm_gemm_qkv<<<512, 256, G_SM_TOTAL>>>(xh, wqh, qh2, ch, wkh, kvh);

    mm_attn<<<1024, 256, A_SM_TOTAL>>>(qh2, kvh, aoh);

    mm_gemm_o<<<dim3(INNER / 128, NROWS / 128), 256, G_SM_TOTAL>>>(
        aoh, woh, out, bo);
}

// round 17
// speedup vs baseline: 1.1734x; 1.0158x over previous
#include <cuda_runtime.h>
#include <cuda_fp16.h>
#include <cstdint>
#include <cstddef>

#define NROWS 8192
#define CROWS 4096
#define QDIM  512
#define INNER 512
#define KVDIM 1024
#define MCTX  2048

// ---------------- static scratch (fp16) --------------------------------------
__device__ __align__(256) __half g_xh [NROWS * QDIM];
__device__ __align__(256) __half g_ch [CROWS * QDIM];
__device__ __align__(256) __half g_wqh[INNER * QDIM];
__device__ __align__(256) __half g_wkh[KVDIM * QDIM];
__device__ __align__(256) __half g_woh[INNER * INNER];
__device__ __align__(256) __half g_qh [NROWS * INNER];
__device__ __align__(256) __half g_kvh[CROWS * KVDIM];
__device__ __align__(256) __half g_aoh[NROWS * INNER];

// ---------------- helpers ----------------------------------------------------
#define SWZ(off) ((off) ^ (((off) >> 3) & 0x70))

static __device__ __forceinline__ uint32_t smem_u32(const void* p) {
    uint32_t a;
    asm("{ .reg .u64 t; cvta.to.shared.u64 t, %1; cvt.u32.u64 %0, t; }"
        : "=r"(a) : "l"(p));
    return a;
}
static __device__ __forceinline__ void ldsm4(uint32_t& r0, uint32_t& r1,
                                             uint32_t& r2, uint32_t& r3, uint32_t a) {
    asm volatile("ldmatrix.sync.aligned.m8n8.x4.shared.b16 {%0,%1,%2,%3}, [%4];"
                 : "=r"(r0), "=r"(r1), "=r"(r2), "=r"(r3) : "r"(a));
}
static __device__ __forceinline__ void ldsm4t(uint32_t& r0, uint32_t& r1,
                                              uint32_t& r2, uint32_t& r3, uint32_t a) {
    asm volatile("ldmatrix.sync.aligned.m8n8.x4.trans.shared.b16 {%0,%1,%2,%3}, [%4];"
                 : "=r"(r0), "=r"(r1), "=r"(r2), "=r"(r3) : "r"(a));
}
static __device__ __forceinline__ void mma16816(float* c, const uint32_t* a,
                                                uint32_t b0, uint32_t b1) {
    asm volatile("mma.sync.aligned.m16n8k16.row.col.f32.f16.f16.f32 "
                 "{%0,%1,%2,%3}, {%4,%5,%6,%7}, {%8,%9}, {%0,%1,%2,%3};"
                 : "+f"(c[0]), "+f"(c[1]), "+f"(c[2]), "+f"(c[3])
                 : "r"(a[0]), "r"(a[1]), "r"(a[2]), "r"(a[3]), "r"(b0), "r"(b1));
}
static __device__ __forceinline__ uint32_t packh(float a, float b) {
    __half2 t = __floats2half2_rn(a, b);
    return *(uint32_t*)&t;
}
static __device__ __forceinline__ uint32_t ex2_h2(uint32_t h2) {
    asm("ex2.approx.f16x2 %0, %0;" : "+r"(h2));
    return h2;
}
#define CP_ASYNC(dst, src) \
    asm volatile("cp.async.cg.shared.global [%0], [%1], 16;" \
                 :: "r"(dst), "l"(src) : "memory")
#define CP_COMMIT() asm volatile("cp.async.commit_group;" ::: "memory")
#define CP_WAIT(n)  asm volatile("cp.async.wait_group %0;" :: "n"(n) : "memory")

// ---------------- conversion kernels ------------------------------------------
__global__ void split_inputs(const float4* __restrict__ x, const float4* __restrict__ c,
                             uint2* __restrict__ xh, uint2* __restrict__ ch,
                             int n1, int n2, float qscale) {
    int i = blockIdx.x * 256 + threadIdx.x;
    const float4* in;
    uint2* oh;
    float scale;
    if (i < n1) { in = x; oh = xh; scale = qscale; }
    else {
        i -= n1;
        if (i >= n2) return;
        in = c; oh = ch; scale = 1.0f;
    }
    float4 v = in[i];
    oh[i] = make_uint2(packh(v.x * scale, v.y * scale),
                       packh(v.z * scale, v.w * scale));
}

__global__ __launch_bounds__(256)
void split_transpose3(const float* __restrict__ w0, const float* __restrict__ w1,
                      const float* __restrict__ w2,
                      __half* __restrict__ oh0, __half* __restrict__ oh1,
                      __half* __restrict__ oh2) {
    const int z = blockIdx.z;
    const float* in = (z == 0) ? w0 : (z == 1) ? w1 : w2;
    __half* oh = (z == 0) ? oh0 : (z == 1) ? oh1 : oh2;
    const int N = (z == 1) ? KVDIM : INNER;
    const int K = QDIM;
    const int n0 = blockIdx.x * 32;
    if (n0 >= N) return;

    __shared__ float t[64][33];
    const int tid = threadIdx.x, tx = tid & 31, ty = tid >> 5;
    const int k0 = blockIdx.y * 64;
    #pragma unroll
    for (int r = ty; r < 64; r += 8)
        t[r][tx] = in[(size_t)(k0 + r) * N + n0 + tx];
    __syncthreads();
    #pragma unroll
    for (int r = ty; r < 32; r += 8) {
        int n = n0 + r;
        *(uint32_t*)(oh + (size_t)n * K + k0 + tx * 2) =
            packh(t[tx * 2][r], t[tx * 2 + 1][r]);
    }
}

// ---------------- HMMA GEMM core: 1-term, 3-stage, 1 sync/chunk ---------------
// Stage = AH (16K) + BH (16K) = 32K; 3 stages = 96K -> occ 2.
#define GSTG(s) ((s) * 32768)
#define G_SM_TOTAL 98304

template <int MODE>   // MODE 1: fp32+bias out; MODE 2: fp16 hi out
static __device__ __forceinline__
void gemm_body(const __half* __restrict__ ah, const __half* __restrict__ bth,
               __half* __restrict__ coh,
               float* __restrict__ cf, const float* __restrict__ bias,
               int M, int N, int K, int bm, int bn, char* sm)
{
    const uint32_t sbase = smem_u32(sm);
    const int tid = threadIdx.x, warp = tid >> 5, lane = tid & 31;
    const int wm = warp >> 2, wn = warp & 3;

    float c[4][4][4] = {};

    const int a_row = (lane & 15), a_cb = (lane >> 4) * 16;
    const int b_row = (lane & 7) + (lane >> 4) * 8, b_cb = ((lane >> 3) & 1) * 16;

    const int NCH = K >> 6;

    #pragma unroll
    for (int p = 0; p < 2; p++) {
        const uint32_t st = sbase + GSTG(p);
        #pragma unroll
        for (int i = 0; i < 4; i++) {
            int idx = tid + i * 256;
            int r = idx >> 3, cc = idx & 7;
            uint32_t off = SWZ(r * 128 + cc * 16);
            CP_ASYNC(st +     0 + off, ah  + (size_t)(bm + r) * K + p * 64 + cc * 8);
            CP_ASYNC(st + 16384 + off, bth + (size_t)(bn + r) * K + p * 64 + cc * 8);
        }
        CP_COMMIT();
    }

    int stg = 0;
    for (int it = 0; it < NCH; it++) {
        if (it + 1 < NCH) CP_WAIT(1); else CP_WAIT(0);
        __syncthreads();   // all warps past chunk it-1 reads; chunk it ready

        const uint32_t ah_s = sbase + GSTG(stg);
        const uint32_t bh_s = ah_s + 16384;

        // refill chunk it+2 into stage (stg+2)%3 (last read at chunk it-1)
        if (it + 2 < NCH) {
            int s2 = stg + 2; if (s2 >= 3) s2 -= 3;
            const uint32_t st = sbase + GSTG(s2);
            const int k0 = (it + 2) << 6;
            #pragma unroll
            for (int i = 0; i < 4; i++) {
                int idx = tid + i * 256;
                int r = idx >> 3, cc = idx & 7;
                uint32_t off = SWZ(r * 128 + cc * 16);
                CP_ASYNC(st +     0 + off, ah  + (size_t)(bm + r) * K + k0 + cc * 8);
                CP_ASYNC(st + 16384 + off, bth + (size_t)(bn + r) * K + k0 + cc * 8);
            }
            CP_COMMIT();
        }

        #pragma unroll
        for (int ks = 0; ks < 4; ks++) {
            uint32_t afh[4][4], bfr[4][2];
            #pragma unroll
            for (int mt = 0; mt < 4; mt++) {
                int row = wm * 64 + mt * 16 + a_row;
                ldsm4(afh[mt][0], afh[mt][1], afh[mt][2], afh[mt][3],
                      ah_s + SWZ(row * 128 + ks * 32 + a_cb));
            }
            #pragma unroll
            for (int np = 0; np < 2; np++) {
                int row = wn * 32 + np * 16 + b_row;
                uint32_t r0, r1, r2, r3;
                ldsm4(r0, r1, r2, r3, bh_s + SWZ(row * 128 + ks * 32 + b_cb));
                bfr[np*2][0] = r0; bfr[np*2][1] = r1;
                bfr[np*2+1][0] = r2; bfr[np*2+1][1] = r3;
            }
            #pragma unroll
            for (int mt = 0; mt < 4; mt++)
                #pragma unroll
                for (int nt = 0; nt < 4; nt++)
                    mma16816(c[mt][nt], afh[mt], bfr[nt][0], bfr[nt][1]);
        }

        if (++stg >= 3) stg = 0;
    }

    #pragma unroll
    for (int mt = 0; mt < 4; mt++) {
        int row0 = bm + wm * 64 + mt * 16 + (lane >> 2);
        #pragma unroll
        for (int nt = 0; nt < 4; nt++) {
            int col = bn + wn * 32 + nt * 8 + (lane & 3) * 2;
            float v0 = c[mt][nt][0], v1 = c[mt][nt][1];
            float v2 = c[mt][nt][2], v3 = c[mt][nt][3];
            if (MODE == 1) {
                float b0 = bias[col], b1 = bias[col + 1];
                *(float2*)(cf + (size_t)row0 * N + col)       = make_float2(v0 + b0, v1 + b1);
                *(float2*)(cf + (size_t)(row0 + 8) * N + col) = make_float2(v2 + b0, v3 + b1);
            } else {
                *(uint32_t*)(coh + (size_t)row0 * N + col)       = packh(v0, v1);
                *(uint32_t*)(coh + (size_t)(row0 + 8) * N + col) = packh(v2, v3);
            }
        }
    }
}

__global__ __launch_bounds__(256, 2)
void mm_gemm_qkv(const __half* __restrict__ xh, const __half* __restrict__ wqh,
                 __half* __restrict__ qh,
                 const __half* __restrict__ ch, const __half* __restrict__ wkh,
                 __half* __restrict__ kvh)
{
    extern __shared__ __align__(128) char sm[];
    const int bid = blockIdx.x;
    if (bid < 256) {
        int bn = (bid & 3) * 128, bm = (bid >> 2) * 128;
        gemm_body<2>(xh, wqh, qh, nullptr, nullptr, NROWS, INNER, QDIM, bm, bn, sm);
    } else {
        int t = bid - 256;
        int bn = (t & 7) * 128, bm = (t >> 3) * 128;
        gemm_body<2>(ch, wkh, kvh, nullptr, nullptr, CROWS, KVDIM, QDIM, bm, bn, sm);
    }
}

__global__ __launch_bounds__(256, 2)
void mm_gemm_o(const __half* __restrict__ aoh, const __half* __restrict__ woh,
               float* __restrict__ out, const float* __restrict__ bias)
{
    extern __shared__ __align__(128) char sm[];
    gemm_body<1>(aoh, woh, nullptr, out, bias,
                 NROWS, INNER, INNER, blockIdx.y * 128, blockIdx.x * 128, sm);
}

// ---------------- HMMA flash attention: 64-q, 3-stage, refill after S ---------
#define AQ_H 0
#define ASTG(s) (8192 + (s) * 32768)    // +0 KH (16K), +16384 VH (16K)
#define ALBUF (8192 + 3 * 32768)         // 106496
#define A_SM_TOTAL 107008

__global__ __launch_bounds__(256, 2)
void mm_attn(const __half* __restrict__ qh, const __half* __restrict__ kvh,
             __half* __restrict__ aoh)
{
    extern __shared__ __align__(128) char sm[];
    const uint32_t sbase = smem_u32(sm);

    const int tid = threadIdx.x, warp = tid >> 5, lane = tid & 31;
    const int wm = warp >> 1, wn = warp & 1;
    const int bx = blockIdx.x;
    const int qt = bx & 63, h = (bx >> 6) & 7, b = bx >> 9;

    const __half* qbh = qh + (size_t)(b * 4096 + qt * 64) * INNER + h * 64;
    const __half* kbh = kvh + (size_t)(b * MCTX) * KVDIM + h * 64;

    // Q tile -> smem (64 rows x 128B)
    #pragma unroll
    for (int i = 0; i < 2; i++) {
        int idx = tid + i * 256;
        int r = idx >> 3, cc = idx & 7;
        *(uint4*)(sm + AQ_H + SWZ(r * 128 + cc * 16)) =
            *(const uint4*)(qbh + (size_t)r * INNER + cc * 8);
    }

    // prefetch chunks 0 and 1
    #pragma unroll
    for (int p = 0; p < 2; p++) {
        const uint32_t st = sbase + ASTG(p);
        #pragma unroll
        for (int i = 0; i < 4; i++) {
            int idx = tid + i * 256;
            int r = idx >> 3, cc = idx & 7;
            uint32_t so = SWZ(r * 128 + cc * 16);
            size_t g = (size_t)(p * 128 + r) * KVDIM + cc * 8;
            CP_ASYNC(st +     0 + so, kbh + g);
            CP_ASYNC(st + 16384 + so, kbh + INNER + g);
        }
        CP_COMMIT();
    }

    const int a_row = (lane & 15), a_cb = (lane >> 4) * 16;
    const int b_row = (lane & 7) + (lane >> 4) * 8, b_cb = ((lane >> 3) & 1) * 16;
    const int v_row = (lane & 7) + ((lane >> 3) & 1) * 8, v_cb = (lane >> 4) * 16;

    // hoist Q fragments: 16 rows x 4 k-steps = 16 regs
    __syncthreads();
    uint32_t qf[4][4];
    #pragma unroll
    for (int ks = 0; ks < 4; ks++)
        ldsm4(qf[ks][0], qf[ks][1], qf[ks][2], qf[ks][3],
              sbase + AQ_H + SWZ((wm * 16 + a_row) * 128 + ks * 32 + a_cb));

    float o[8][4] = {};
    float lp[2] = {};

    int stg = 0;
    for (int it = 0; it < 16; it++) {
        if (it + 1 < 16) CP_WAIT(1); else CP_WAIT(0);
        __syncthreads();

        const uint32_t kh_s = sbase + ASTG(stg);
        const uint32_t vh_s = kh_s + 16384;

        // ---- S = Qh Kh^T over this warp's 64-key half ----
        float s[8][4] = {};
        #pragma unroll
        for (int ks = 0; ks < 4; ks++) {
            uint32_t bh2[8][2];
            #pragma unroll
            for (int np = 0; np < 4; np++) {
                int row = wn * 64 + np * 16 + b_row;
                uint32_t r0, r1, r2, r3;
                ldsm4(r0, r1, r2, r3, kh_s + SWZ(row * 128 + ks * 32 + b_cb));
                bh2[np*2][0] = r0; bh2[np*2][1] = r1;
                bh2[np*2+1][0] = r2; bh2[np*2+1][1] = r3;
            }
            #pragma unroll
            for (int nt = 0; nt < 8; nt++)
                mma16816(s[nt], qf[ks], bh2[nt][0], bh2[nt][1]);
        }

        // refill chunk it+2 (stage last read at it-1) — after S MMAs so the
        // tensor pipe starts immediately post-barrier
        if (it + 2 < 16) {
            int s2 = stg + 2; if (s2 >= 3) s2 -= 3;
            const uint32_t st = sbase + ASTG(s2);
            #pragma unroll
            for (int i = 0; i < 4; i++) {
                int idx = tid + i * 256;
                int r = idx >> 3, cc = idx & 7;
                uint32_t so = SWZ(r * 128 + cc * 16);
                size_t g = (size_t)((it + 2) * 128 + r) * KVDIM + cc * 8;
                CP_ASYNC(st +     0 + so, kbh + g);
                CP_ASYNC(st + 16384 + so, kbh + INNER + g);
            }
            CP_COMMIT();
        }

        // ---- P = exp2(S) fp16x2; l fp32 ----
        uint32_t pa[4][4];
        #pragma unroll
        for (int ks2 = 0; ks2 < 4; ks2++)
            #pragma unroll
            for (int jj = 0; jj < 2; jj++) {
                float* sv = s[2 * ks2 + jj];
                uint32_t h01 = ex2_h2(packh(sv[0], sv[1]));
                uint32_t h23 = ex2_h2(packh(sv[2], sv[3]));
                pa[ks2][jj * 2]     = h01;
                pa[ks2][jj * 2 + 1] = h23;
                float2 f01 = __half22float2(*(__half2*)&h01);
                float2 f23 = __half22float2(*(__half2*)&h23);
                lp[0] += f01.x + f01.y;
                lp[1] += f23.x + f23.y;
            }

        // ---- O += Ph Vh (this key half) ----
        #pragma unroll
        for (int ks2 = 0; ks2 < 4; ks2++) {
            const int key0 = wn * 64 + ks2 * 16;
            uint32_t bh2[8][2];
            #pragma unroll
            for (int D = 0; D < 4; D++) {
                uint32_t so = SWZ((key0 + v_row) * 128 + D * 32 + v_cb);
                uint32_t r0, r1, r2, r3;
                ldsm4t(r0, r1, r2, r3, vh_s + so);
                bh2[2*D][0] = r0; bh2[2*D][1] = r1;
                bh2[2*D+1][0] = r2; bh2[2*D+1][1] = r3;
            }
            #pragma unroll
            for (int dt = 0; dt < 8; dt++)
                mma16816(o[dt], pa[ks2], bh2[dt][0], bh2[dt][1]);
        }

        if (++stg >= 3) stg = 0;
    }
    __syncthreads();

    // ---- l: quad reduce, stash per key-half ----
    float* lbuf = (float*)(sm + ALBUF);
    #pragma unroll
    for (int rr = 0; rr < 2; rr++) {
        float v = lp[rr];
        v += __shfl_xor_sync(0xFFFFFFFF, v, 1);
        v += __shfl_xor_sync(0xFFFFFFFF, v, 2);
        if ((lane & 3) == 0)
            lbuf[wn * 64 + wm * 16 + rr * 8 + (lane >> 2)] = v;
    }
    __syncthreads();

    // ---- O reduce across wn via smem (reuse stage 0: 16KB) ----
    float* obuf = (float*)(sm + ASTG(0));
    if (wn == 1) {
        int r0 = wm * 16 + (lane >> 2);
        #pragma unroll
        for (int dt = 0; dt < 8; dt++) {
            int col = dt * 8 + (lane & 3) * 2;
            *(float2*)(obuf + r0 * 64 + col)       = make_float2(o[dt][0], o[dt][1]);
            *(float2*)(obuf + (r0 + 8) * 64 + col) = make_float2(o[dt][2], o[dt][3]);
        }
    }
    __syncthreads();
    if (wn == 0) {
        int r0 = wm * 16 + (lane >> 2);
        int r1 = r0 + 8;
        float inv0 = 1.0f / (lbuf[r0] + lbuf[64 + r0]);
        float inv1 = 1.0f / (lbuf[r1] + lbuf[64 + r1]);
        size_t g0 = (size_t)(b * 4096 + qt * 64 + r0) * INNER + h * 64;
        size_t g1 = (size_t)(b * 4096 + qt * 64 + r1) * INNER + h * 64;
        #pragma unroll
        for (int dt = 0; dt < 8; dt++) {
            int col = dt * 8 + (lane & 3) * 2;
            float2 p0 = *(float2*)(obuf + r0 * 64 + col);
            float2 p1 = *(float2*)(obuf + r1 * 64 + col);
            *(uint32_t*)(aoh + g0 + col) =
                packh((o[dt][0] + p0.x) * inv0, (o[dt][1] + p0.y) * inv0);
            *(uint32_t*)(aoh + g1 + col) =
                packh((o[dt][2] + p1.x) * inv1, (o[dt][3] + p1.y) * inv1);
        }
    }
}

// ---------------------------------------------------------------------------
extern "C" void kernel_launch(void* const* d_in, const int* in_sizes, int n_in,
                              void* d_out, int out_size)
{
    const float* x   = (const float*)d_in[0];
    const float* ctx = (const float*)d_in[1];
    const float* Wq  = (const float*)d_in[2];
    const float* Wkv = (const float*)d_in[3];
    const float* Wo  = (const float*)d_in[4];
    const float* bo  = (const float*)d_in[5];
    float* out = (float*)d_out;

    __half *xh, *ch, *wqh, *wkh, *woh, *qh2, *kvh, *aoh;
    cudaGetSymbolAddress((void**)&xh,  g_xh);
    cudaGetSymbolAddress((void**)&ch,  g_ch);
    cudaGetSymbolAddress((void**)&wqh, g_wqh);
    cudaGetSymbolAddress((void**)&wkh, g_wkh);
    cudaGetSymbolAddress((void**)&woh, g_woh);
    cudaGetSymbolAddress((void**)&qh2, g_qh);
    cudaGetSymbolAddress((void**)&kvh, g_kvh);
    cudaGetSymbolAddress((void**)&aoh, g_aoh);

    cudaFuncSetAttribute(mm_gemm_qkv, cudaFuncAttributeMaxDynamicSharedMemorySize, G_SM_TOTAL);
    cudaFuncSetAttribute(mm_gemm_o,   cudaFuncAttributeMaxDynamicSharedMemorySize, G_SM_TOTAL);
    cudaFuncSetAttribute(mm_attn,     cudaFuncAttributeMaxDynamicSharedMemorySize, A_SM_TOTAL);

    // x feeds only Wq: pre-scale by log2(e)/8 so attn softmax is exp2(S)
    const float QSCALE = 0.18033688011112042f;
    int n1 = NROWS * QDIM / 4, n2 = CROWS * QDIM / 4;
    split_inputs<<<(n1 + n2 + 255) / 256, 256>>>(
        (const float4*)x, (const float4*)ctx, (uint2*)xh, (uint2*)ch, n1, n2, QSCALE);
    split_transpose3<<<dim3(KVDIM / 32, QDIM / 64, 3), 256>>>(
        Wq, Wkv, Wo, wqh, wkh, woh);

    mm_gemm_qkv<<<512, 256, G_SM_TOTAL>>>(xh, wqh, qh2, ch, wkh, kvh);

    mm_attn<<<1024, 256, A_SM_TOTAL>>>(qh2, kvh, aoh);

    mm_gemm_o<<<dim3(INNER / 128, NROWS / 128), 256, G_SM_TOTAL>>>(
        aoh, woh, out, bo);
}